// round 3
// baseline (speedup 1.0000x reference)
#include <cuda_runtime.h>

#define B_ 128
#define N_ 512
#define C_ 128
#define W_ 128
#define MASK_FILL_ (-1e-6f)

// Scratch (static __device__ arrays: allocation-free per harness rules)
__device__ float g_q[(size_t)B_ * N_ * W_];
__device__ float g_k[(size_t)B_ * N_ * W_];
__device__ float g_v[(size_t)B_ * N_ * W_];
__device__ int   g_vl[B_];

// ---------------------------------------------------------------------------
// valid_len decode: reference asks for int64, but JAX without x64 canonicalizes
// to int32. Detect at runtime: interpret first 64 entries as int64; if any is
// outside [0, N) the buffer is really int32 (high word of the pair is another
// nonzero valid_len with overwhelming probability).
// ---------------------------------------------------------------------------
__global__ void decode_vl_kernel(const void* __restrict__ raw) {
    __shared__ int bad;
    int t = threadIdx.x;
    if (t == 0) bad = 0;
    __syncthreads();
    if (t < 64) {
        long long v = ((const long long*)raw)[t];
        if (v < 0 || v >= N_) atomicOr(&bad, 1);
    }
    __syncthreads();
    if (t < B_) {
        g_vl[t] = bad ? ((const int*)raw)[t]
                      : (int)((const long long*)raw)[t];
    }
}

// Load a 64x128 fp32 tile (row-major, contiguous) into padded smem [64][129].
__device__ __forceinline__ void load_tile64(float (*dst)[129],
                                            const float* __restrict__ src,
                                            int tid) {
    const float4* s4 = (const float4*)src;
#pragma unroll
    for (int i = tid; i < 64 * 32; i += 256) {
        float4 v = s4[i];
        int r = i >> 5, c = (i & 31) << 2;
        dst[r][c]     = v.x;
        dst[r][c + 1] = v.y;
        dst[r][c + 2] = v.z;
        dst[r][c + 3] = v.w;
    }
}

// ---------------------------------------------------------------------------
// QKV projection: [65536,128] x [128,128] GEMM, blockIdx.y selects Q/K/V.
// BM=64, BN=128 (full W in smem), 256 threads, 4x8 microtile.
// K rows fully beyond valid_len are never read by attention -> skip them.
// ---------------------------------------------------------------------------
__global__ __launch_bounds__(256)
void qkv_kernel(const float* __restrict__ x,
                const float* __restrict__ Wq, const float* __restrict__ bq,
                const float* __restrict__ Wk, const float* __restrict__ bk,
                const float* __restrict__ Wv, const float* __restrict__ bv) {
    extern __shared__ float sm[];
    float (*xs)[129] = (float(*)[129])sm;       // 64*129
    float* ws = sm + 64 * 129;                  // 128*128
    float* bs = ws + 128 * 128;                 // 128

    const float* Wm;
    const float* bias;
    float* outp;
    int which = blockIdx.y;
    if (which == 0)      { Wm = Wq; bias = bq; outp = g_q; }
    else if (which == 1) { Wm = Wk; bias = bk; outp = g_k; }
    else                 { Wm = Wv; bias = bv; outp = g_v; }

    int row0 = blockIdx.x * 64;
    if (which == 1) {
        int bidx = row0 / N_;
        if ((row0 % N_) > g_vl[bidx]) return;  // fully-masked K tile: unused
    }

    int tid = threadIdx.x;

    // Stage W (16384 floats) and bias
    {
        const float4* W4 = (const float4*)Wm;
        float4* ws4 = (float4*)ws;
#pragma unroll
        for (int i = tid; i < 128 * 32; i += 256) ws4[i] = W4[i];
        if (tid < 128) bs[tid] = bias[tid];
    }
    load_tile64(xs, x + (size_t)row0 * C_, tid);
    __syncthreads();

    int tx = tid & 15, ty = tid >> 4;
    float acc[4][8];
#pragma unroll
    for (int i = 0; i < 4; i++)
#pragma unroll
        for (int j = 0; j < 8; j++) acc[i][j] = 0.f;

#pragma unroll 4
    for (int k = 0; k < 128; k++) {
        float a[4], bb[8];
#pragma unroll
        for (int i = 0; i < 4; i++) a[i] = xs[4 * ty + i][k];
#pragma unroll
        for (int j = 0; j < 8; j++) bb[j] = ws[k * 128 + tx + 16 * j];
#pragma unroll
        for (int i = 0; i < 4; i++)
#pragma unroll
            for (int j = 0; j < 8; j++)
                acc[i][j] = fmaf(a[i], bb[j], acc[i][j]);
    }

#pragma unroll
    for (int i = 0; i < 4; i++) {
        size_t r = (size_t)row0 + 4 * ty + i;
#pragma unroll
        for (int j = 0; j < 8; j++) {
            int c = tx + 16 * j;
            outp[r * W_ + c] = acc[i][j] + bs[c];
        }
    }
}

// ---------------------------------------------------------------------------
// Attention: one block per (batch, 64-row q tile). 256 threads.
// Phase 1: scores[64][512] = Qtile @ K^T (only m-tiles with any kept column).
// Phase 2: masked softmax (mask value -1e-6 participates in max & sum).
//          Masked columns share one weight per row -> folded analytically.
// Phase 3: out = attn @ V over kept tiles + wm * Vsuffix.
// ---------------------------------------------------------------------------
__global__ __launch_bounds__(256, 1)
void attn_kernel(float* __restrict__ outp) {
    extern __shared__ float sm[];
    float (*qs)[129] = (float(*)[129])sm;                    // 64*129
    float (*ks)[129] = (float(*)[129])(sm + 64 * 129);       // 64*129 (K, then V)
    float (*sc)[513] = (float(*)[513])(sm + 2 * 64 * 129);   // 64*513
    float* rinv = sm + 2 * 64 * 129 + 64 * 513;              // 64
    float* rwm  = rinv + 64;                                 // 64
    float* vsuf = rwm + 64;                                  // 128
    float* vtmp = vsuf + 128;                                // 256

    int b    = blockIdx.x;
    int row0 = blockIdx.y * 64;
    int tid  = threadIdx.x;
    int tx = tid & 15, ty = tid >> 4;
    int lane = tid & 31, warp = tid >> 5;

    const float* qg = g_q + ((size_t)b * N_ + row0) * W_;
    const float* kg = g_k + (size_t)b * N_ * W_;
    const float* vg = g_v + (size_t)b * N_ * W_;
    int vl = g_vl[b];
    int ktiles = (vl >> 6) + 1;  // m-tiles containing at least one kept column

    // V suffix sum over masked rows (m > vl): 2 threads per column
    {
        int col = tid & 127, half = tid >> 7;
        float s = 0.f;
        for (int m = vl + 1 + half; m < N_; m += 2) s += vg[(size_t)m * W_ + col];
        vtmp[half * 128 + col] = s;
    }
    load_tile64(qs, qg, tid);
    __syncthreads();
    if (tid < 128) vsuf[tid] = vtmp[tid] + vtmp[128 + tid];

    // ---- Phase 1: scores ----
    for (int mt = 0; mt < ktiles; mt++) {
        __syncthreads();
        load_tile64(ks, kg + (size_t)mt * 64 * W_, tid);
        __syncthreads();
        float acc[4][4];
#pragma unroll
        for (int i = 0; i < 4; i++)
#pragma unroll
            for (int j = 0; j < 4; j++) acc[i][j] = 0.f;
#pragma unroll 4
        for (int k = 0; k < 128; k++) {
            float a[4], bb[4];
#pragma unroll
            for (int i = 0; i < 4; i++) a[i] = qs[4 * ty + i][k];
#pragma unroll
            for (int j = 0; j < 4; j++) bb[j] = ks[tx + 16 * j][k];
#pragma unroll
            for (int i = 0; i < 4; i++)
#pragma unroll
                for (int j = 0; j < 4; j++)
                    acc[i][j] = fmaf(a[i], bb[j], acc[i][j]);
        }
#pragma unroll
        for (int i = 0; i < 4; i++)
#pragma unroll
            for (int j = 0; j < 4; j++)
                sc[4 * ty + i][mt * 64 + tx + 16 * j] = acc[i][j];
    }
    __syncthreads();

    // ---- Phase 2: masked softmax (warp handles 8 rows) ----
    for (int rr = 0; rr < 8; rr++) {
        int r = warp * 8 + rr;
        float vals[16];
        float mx = -3.0e38f;
#pragma unroll
        for (int kk = 0; kk < 16; kk++) {
            int col = lane + 32 * kk;
            float s = sc[r][col];
            vals[kk] = s;
            if (col <= vl) mx = fmaxf(mx, s);
        }
        if (vl < N_ - 1) mx = fmaxf(mx, MASK_FILL_);  // masked entries join max
#pragma unroll
        for (int off = 16; off > 0; off >>= 1)
            mx = fmaxf(mx, __shfl_xor_sync(0xffffffffu, mx, off));
        float sum = 0.f;
#pragma unroll
        for (int kk = 0; kk < 16; kk++) {
            int col = lane + 32 * kk;
            float e = (col <= vl) ? __expf(vals[kk] - mx) : 0.f;
            sc[r][col] = e;
            sum += e;
        }
#pragma unroll
        for (int off = 16; off > 0; off >>= 1)
            sum += __shfl_xor_sync(0xffffffffu, sum, off);
        float wm = __expf(MASK_FILL_ - mx);          // shared masked weight
        sum += (float)(N_ - 1 - vl) * wm;
        if (lane == 0) { rinv[r] = 1.f / sum; rwm[r] = wm / sum; }
    }
    __syncthreads();

    // ---- Phase 3: AV over kept tiles ----
    float oacc[4][8];
#pragma unroll
    for (int i = 0; i < 4; i++)
#pragma unroll
        for (int j = 0; j < 8; j++) oacc[i][j] = 0.f;

    for (int mt = 0; mt < ktiles; mt++) {
        __syncthreads();
        load_tile64(ks, vg + (size_t)mt * 64 * W_, tid);
        __syncthreads();
#pragma unroll 2
        for (int mm = 0; mm < 64; mm++) {
            float a[4], bb[8];
#pragma unroll
            for (int i = 0; i < 4; i++) a[i] = sc[4 * ty + i][mt * 64 + mm];
#pragma unroll
            for (int j = 0; j < 8; j++) bb[j] = ks[mm][tx + 16 * j];
#pragma unroll
            for (int i = 0; i < 4; i++)
#pragma unroll
                for (int j = 0; j < 8; j++)
                    oacc[i][j] = fmaf(a[i], bb[j], oacc[i][j]);
        }
    }

    // ---- Epilogue: normalize + masked-columns analytic contribution ----
#pragma unroll
    for (int i = 0; i < 4; i++) {
        int r = 4 * ty + i;
        float inv = rinv[r], wn = rwm[r];
#pragma unroll
        for (int j = 0; j < 8; j++) {
            int c = tx + 16 * j;
            outp[((size_t)b * N_ + row0 + r) * W_ + c] =
                oacc[i][j] * inv + wn * vsuf[c];
        }
    }
}

// ---------------------------------------------------------------------------
// Launch
// ---------------------------------------------------------------------------
#define QKV_SMEM  ((64 * 129 + 128 * 128 + 128) * (int)sizeof(float))
#define ATTN_SMEM ((2 * 64 * 129 + 64 * 513 + 64 + 64 + 128 + 256) * (int)sizeof(float))

extern "C" void kernel_launch(void* const* d_in, const int* in_sizes, int n_in,
                              void* d_out, int out_size) {
    const float* x  = (const float*)d_in[0];
    const float* Wq = (const float*)d_in[1];
    const float* bq = (const float*)d_in[2];
    const float* Wk = (const float*)d_in[3];
    const float* bk = (const float*)d_in[4];
    const float* Wv = (const float*)d_in[5];
    const float* bv = (const float*)d_in[6];
    const void*  vl = d_in[7];
    float* outp = (float*)d_out;

    cudaFuncSetAttribute(qkv_kernel,
                         cudaFuncAttributeMaxDynamicSharedMemorySize, QKV_SMEM);
    cudaFuncSetAttribute(attn_kernel,
                         cudaFuncAttributeMaxDynamicSharedMemorySize, ATTN_SMEM);

    decode_vl_kernel<<<1, 128>>>(vl);
    qkv_kernel<<<dim3((B_ * N_) / 64, 3), 256, QKV_SMEM>>>(x, Wq, bq, Wk, bk, Wv, bv);
    attn_kernel<<<dim3(B_, N_ / 64), 256, ATTN_SMEM>>>(outp);
}

// round 4
// speedup vs baseline: 1.0503x; 1.0503x over previous
#include <cuda_runtime.h>

#define B_ 128
#define N_ 512
#define C_ 128
#define W_ 128
#define MASK_FILL_ (-1e-6f)

// Scratch (static __device__ arrays: allocation-free per harness rules)
__device__ float g_q[(size_t)B_ * N_ * W_];
__device__ float g_k[(size_t)B_ * N_ * W_];
__device__ float g_v[(size_t)B_ * N_ * W_];
__device__ int   g_vl[B_];

// ---------------------------------------------------------------------------
// valid_len decode: reference asks for int64, but JAX without x64 canonicalizes
// to int32. Detect at runtime: interpret first 64 entries as int64; if any is
// outside [0, N) the buffer is really int32 (high word of the pair is another
// nonzero valid_len with overwhelming probability).
// ---------------------------------------------------------------------------
__global__ void decode_vl_kernel(const void* __restrict__ raw) {
    __shared__ int bad;
    int t = threadIdx.x;
    if (t == 0) bad = 0;
    __syncthreads();
    if (t < 64) {
        long long v = ((const long long*)raw)[t];
        if (v < 0 || v >= N_) atomicOr(&bad, 1);
    }
    __syncthreads();
    if (t < B_) {
        g_vl[t] = bad ? ((const int*)raw)[t]
                      : (int)((const long long*)raw)[t];
    }
}

// Load a 64x128 fp32 tile (row-major, contiguous) into padded smem [64][129].
__device__ __forceinline__ void load_tile64(float (*dst)[129],
                                            const float* __restrict__ src,
                                            int tid) {
    const float4* s4 = (const float4*)src;
#pragma unroll
    for (int i = tid; i < 64 * 32; i += 256) {
        float4 v = s4[i];
        int r = i >> 5, c = (i & 31) << 2;
        dst[r][c]     = v.x;
        dst[r][c + 1] = v.y;
        dst[r][c + 2] = v.z;
        dst[r][c + 3] = v.w;
    }
}

// ---------------------------------------------------------------------------
// QKV projection: [65536,128] x [128,128] GEMM, blockIdx.y selects Q/K/V.
// BM=64, BN=128 (full W in smem), 256 threads, 4x8 microtile.
// K rows fully beyond valid_len are never read by attention -> skip them.
// ---------------------------------------------------------------------------
__global__ __launch_bounds__(256)
void qkv_kernel(const float* __restrict__ x,
                const float* __restrict__ Wq, const float* __restrict__ bq,
                const float* __restrict__ Wk, const float* __restrict__ bk,
                const float* __restrict__ Wv, const float* __restrict__ bv) {
    extern __shared__ float sm[];
    float (*xs)[129] = (float(*)[129])sm;       // 64*129
    float* ws = sm + 64 * 129;                  // 128*128
    float* bs = ws + 128 * 128;                 // 128

    const float* Wm;
    const float* bias;
    float* outp;
    int which = blockIdx.y;
    if (which == 0)      { Wm = Wq; bias = bq; outp = g_q; }
    else if (which == 1) { Wm = Wk; bias = bk; outp = g_k; }
    else                 { Wm = Wv; bias = bv; outp = g_v; }

    int row0 = blockIdx.x * 64;
    if (which == 1) {
        int bidx = row0 / N_;
        if ((row0 % N_) > g_vl[bidx]) return;  // fully-masked K tile: unused
    }

    int tid = threadIdx.x;

    // Stage W (16384 floats) and bias
    {
        const float4* W4 = (const float4*)Wm;
        float4* ws4 = (float4*)ws;
#pragma unroll
        for (int i = tid; i < 128 * 32; i += 256) ws4[i] = W4[i];
        if (tid < 128) bs[tid] = bias[tid];
    }
    load_tile64(xs, x + (size_t)row0 * C_, tid);
    __syncthreads();

    int tx = tid & 15, ty = tid >> 4;
    float acc[4][8];
#pragma unroll
    for (int i = 0; i < 4; i++)
#pragma unroll
        for (int j = 0; j < 8; j++) acc[i][j] = 0.f;

#pragma unroll 4
    for (int k = 0; k < 128; k++) {
        float a[4], bb[8];
#pragma unroll
        for (int i = 0; i < 4; i++) a[i] = xs[4 * ty + i][k];
#pragma unroll
        for (int j = 0; j < 8; j++) bb[j] = ws[k * 128 + tx + 16 * j];
#pragma unroll
        for (int i = 0; i < 4; i++)
#pragma unroll
            for (int j = 0; j < 8; j++)
                acc[i][j] = fmaf(a[i], bb[j], acc[i][j]);
    }

#pragma unroll
    for (int i = 0; i < 4; i++) {
        size_t r = (size_t)row0 + 4 * ty + i;
#pragma unroll
        for (int j = 0; j < 8; j++) {
            int c = tx + 16 * j;
            outp[r * W_ + c] = acc[i][j] + bs[c];
        }
    }
}

// ---------------------------------------------------------------------------
// Attention: one block per (batch, 64-row q tile). 256 threads.
// Phase 1: scores[64][512] = Qtile @ K^T (only m-tiles with any kept column).
// Phase 2: masked softmax (mask value -1e-6 participates in max & sum).
//          Masked columns share one weight per row -> folded analytically.
// Phase 3: out = attn @ V over kept tiles + wm * Vsuffix.
// ---------------------------------------------------------------------------
__global__ __launch_bounds__(256, 1)
void attn_kernel(float* __restrict__ outp) {
    extern __shared__ float sm[];
    float (*qs)[129] = (float(*)[129])sm;                    // 64*129
    float (*ks)[129] = (float(*)[129])(sm + 64 * 129);       // 64*129 (K, then V)
    float (*sc)[513] = (float(*)[513])(sm + 2 * 64 * 129);   // 64*513
    float* rinv = sm + 2 * 64 * 129 + 64 * 513;              // 64
    float* rwm  = rinv + 64;                                 // 64
    float* vsuf = rwm + 64;                                  // 128
    float* vtmp = vsuf + 128;                                // 256

    int b    = blockIdx.x;
    int row0 = blockIdx.y * 64;
    int tid  = threadIdx.x;
    int tx = tid & 15, ty = tid >> 4;
    int lane = tid & 31, warp = tid >> 5;

    const float* qg = g_q + ((size_t)b * N_ + row0) * W_;
    const float* kg = g_k + (size_t)b * N_ * W_;
    const float* vg = g_v + (size_t)b * N_ * W_;
    int vl = g_vl[b];
    int ktiles = (vl >> 6) + 1;  // m-tiles containing at least one kept column

    // V suffix sum over masked rows (m > vl): 2 threads per column
    {
        int col = tid & 127, half = tid >> 7;
        float s = 0.f;
        for (int m = vl + 1 + half; m < N_; m += 2) s += vg[(size_t)m * W_ + col];
        vtmp[half * 128 + col] = s;
    }
    load_tile64(qs, qg, tid);
    __syncthreads();
    if (tid < 128) vsuf[tid] = vtmp[tid] + vtmp[128 + tid];

    // ---- Phase 1: scores ----
    for (int mt = 0; mt < ktiles; mt++) {
        __syncthreads();
        load_tile64(ks, kg + (size_t)mt * 64 * W_, tid);
        __syncthreads();
        float acc[4][4];
#pragma unroll
        for (int i = 0; i < 4; i++)
#pragma unroll
            for (int j = 0; j < 4; j++) acc[i][j] = 0.f;
#pragma unroll 4
        for (int k = 0; k < 128; k++) {
            float a[4], bb[4];
#pragma unroll
            for (int i = 0; i < 4; i++) a[i] = qs[4 * ty + i][k];
#pragma unroll
            for (int j = 0; j < 4; j++) bb[j] = ks[tx + 16 * j][k];
#pragma unroll
            for (int i = 0; i < 4; i++)
#pragma unroll
                for (int j = 0; j < 4; j++)
                    acc[i][j] = fmaf(a[i], bb[j], acc[i][j]);
        }
#pragma unroll
        for (int i = 0; i < 4; i++)
#pragma unroll
            for (int j = 0; j < 4; j++)
                sc[4 * ty + i][mt * 64 + tx + 16 * j] = acc[i][j];
    }
    __syncthreads();

    // ---- Phase 2: masked softmax (warp handles 8 rows) ----
    for (int rr = 0; rr < 8; rr++) {
        int r = warp * 8 + rr;
        float vals[16];
        float mx = -3.0e38f;
#pragma unroll
        for (int kk = 0; kk < 16; kk++) {
            int col = lane + 32 * kk;
            float s = sc[r][col];
            vals[kk] = s;
            if (col <= vl) mx = fmaxf(mx, s);
        }
        if (vl < N_ - 1) mx = fmaxf(mx, MASK_FILL_);  // masked entries join max
#pragma unroll
        for (int off = 16; off > 0; off >>= 1)
            mx = fmaxf(mx, __shfl_xor_sync(0xffffffffu, mx, off));
        float sum = 0.f;
#pragma unroll
        for (int kk = 0; kk < 16; kk++) {
            int col = lane + 32 * kk;
            float e = (col <= vl) ? __expf(vals[kk] - mx) : 0.f;
            sc[r][col] = e;
            sum += e;
        }
#pragma unroll
        for (int off = 16; off > 0; off >>= 1)
            sum += __shfl_xor_sync(0xffffffffu, sum, off);
        float wm = __expf(MASK_FILL_ - mx);          // shared masked weight
        sum += (float)(N_ - 1 - vl) * wm;
        if (lane == 0) { rinv[r] = 1.f / sum; rwm[r] = wm / sum; }
    }
    __syncthreads();

    // ---- Phase 3: AV over kept tiles ----
    float oacc[4][8];
#pragma unroll
    for (int i = 0; i < 4; i++)
#pragma unroll
        for (int j = 0; j < 8; j++) oacc[i][j] = 0.f;

    for (int mt = 0; mt < ktiles; mt++) {
        __syncthreads();
        load_tile64(ks, vg + (size_t)mt * 64 * W_, tid);
        __syncthreads();
#pragma unroll 2
        for (int mm = 0; mm < 64; mm++) {
            float a[4], bb[8];
#pragma unroll
            for (int i = 0; i < 4; i++) a[i] = sc[4 * ty + i][mt * 64 + mm];
#pragma unroll
            for (int j = 0; j < 8; j++) bb[j] = ks[mm][tx + 16 * j];
#pragma unroll
            for (int i = 0; i < 4; i++)
#pragma unroll
                for (int j = 0; j < 8; j++)
                    oacc[i][j] = fmaf(a[i], bb[j], oacc[i][j]);
        }
    }

    // ---- Epilogue: normalize + masked-columns analytic contribution ----
#pragma unroll
    for (int i = 0; i < 4; i++) {
        int r = 4 * ty + i;
        float inv = rinv[r], wn = rwm[r];
#pragma unroll
        for (int j = 0; j < 8; j++) {
            int c = tx + 16 * j;
            outp[((size_t)b * N_ + row0 + r) * W_ + c] =
                oacc[i][j] * inv + wn * vsuf[c];
        }
    }
}

// ---------------------------------------------------------------------------
// Launch
// ---------------------------------------------------------------------------
#define QKV_SMEM  ((64 * 129 + 128 * 128 + 128) * (int)sizeof(float))
#define ATTN_SMEM ((2 * 64 * 129 + 64 * 513 + 64 + 64 + 128 + 256) * (int)sizeof(float))

extern "C" void kernel_launch(void* const* d_in, const int* in_sizes, int n_in,
                              void* d_out, int out_size) {
    const float* x  = (const float*)d_in[0];
    const float* Wq = (const float*)d_in[1];
    const float* bq = (const float*)d_in[2];
    const float* Wk = (const float*)d_in[3];
    const float* bk = (const float*)d_in[4];
    const float* Wv = (const float*)d_in[5];
    const float* bv = (const float*)d_in[6];
    const void*  vl = d_in[7];
    float* outp = (float*)d_out;

    cudaFuncSetAttribute(qkv_kernel,
                         cudaFuncAttributeMaxDynamicSharedMemorySize, QKV_SMEM);
    cudaFuncSetAttribute(attn_kernel,
                         cudaFuncAttributeMaxDynamicSharedMemorySize, ATTN_SMEM);

    decode_vl_kernel<<<1, 128>>>(vl);
    qkv_kernel<<<dim3((B_ * N_) / 64, 3), 256, QKV_SMEM>>>(x, Wq, bq, Wk, bk, Wv, bv);
    attn_kernel<<<dim3(B_, N_ / 64), 256, ATTN_SMEM>>>(outp);
}

// round 6
// speedup vs baseline: 1.7200x; 1.6376x over previous
#include <cuda_runtime.h>
#include <cuda_bf16.h>
#include <cstdint>

#define B_ 128
#define N_ 512
#define C_ 128
#define W_ 128
#define MASKF (-1e-6f)

#define TILE_U32 8192   // unpadded 128x128 bf16 tile = 128 rows x 64 u32
#define PROW 68         // padded SMEM row stride in u32 (136 halves, 272B)
#define PT_U32 (128 * PROW)  // 8704 u32 per padded tile

// ---- global scratch (static: allocation-free) ----
__device__ __align__(16) uint32_t g_qh[(size_t)B_ * 4 * TILE_U32];
__device__ __align__(16) uint32_t g_ql[(size_t)B_ * 4 * TILE_U32];
__device__ __align__(16) uint32_t g_kh[(size_t)B_ * 4 * TILE_U32];
__device__ __align__(16) uint32_t g_kl[(size_t)B_ * 4 * TILE_U32];
__device__ __align__(16) uint32_t g_vth[(size_t)B_ * 4 * TILE_U32];  // V^T tiles [w][m]
__device__ __align__(16) uint32_t g_vtl[(size_t)B_ * 4 * TILE_U32];
__device__ __align__(16) uint32_t g_wth[3 * TILE_U32];  // W^T hi (q,k,v)
__device__ __align__(16) uint32_t g_wtl[3 * TILE_U32];
__device__ float g_vsuf[B_ * W_];
__device__ int   g_vl[B_];

// ---- helpers ----
__device__ __forceinline__ void split_pack(float f0, float f1,
                                           uint32_t& h, uint32_t& l) {
    __nv_bfloat16 h0 = __float2bfloat16_rn(f0);
    __nv_bfloat16 h1 = __float2bfloat16_rn(f1);
    __nv_bfloat16 l0 = __float2bfloat16_rn(f0 - __bfloat162float(h0));
    __nv_bfloat16 l1 = __float2bfloat16_rn(f1 - __bfloat162float(h1));
    h = (uint32_t)__bfloat16_as_ushort(h0) | ((uint32_t)__bfloat16_as_ushort(h1) << 16);
    l = (uint32_t)__bfloat16_as_ushort(l0) | ((uint32_t)__bfloat16_as_ushort(l1) << 16);
}
__device__ __forceinline__ void split1(float f, unsigned short& h, unsigned short& l) {
    __nv_bfloat16 hh = __float2bfloat16_rn(f);
    __nv_bfloat16 ll = __float2bfloat16_rn(f - __bfloat162float(hh));
    h = __bfloat16_as_ushort(hh);
    l = __bfloat16_as_ushort(ll);
}
// mma.sync m16n8k16 bf16 (generic PTX, sm_80+; lowers to HMMA on sm_103a)
__device__ __forceinline__ void mma16816(float c[4], uint32_t a0, uint32_t a1,
                                         uint32_t a2, uint32_t a3,
                                         uint32_t b0, uint32_t b1) {
    asm volatile(
        "mma.sync.aligned.m16n8k16.row.col.f32.bf16.bf16.f32 "
        "{%0,%1,%2,%3}, {%4,%5,%6,%7}, {%8,%9}, {%0,%1,%2,%3};"
        : "+f"(c[0]), "+f"(c[1]), "+f"(c[2]), "+f"(c[3])
        : "r"(a0), "r"(a1), "r"(a2), "r"(a3), "r"(b0), "r"(b1));
}
// copy unpadded global tile (128x64 u32) -> padded SMEM (stride PROW)
__device__ __forceinline__ void copy_pad(uint32_t* dst, const uint32_t* src, int tid) {
    const float4* s4 = (const float4*)src;
    float4* d4 = (float4*)dst;
#pragma unroll
    for (int i = tid; i < 2048; i += 256) d4[(i >> 4) * 17 + (i & 15)] = s4[i];
}

// ---- decode valid_len (runtime int64-vs-int32 detect) + zero vsuf ----
__global__ void decode_vl_kernel(const void* __restrict__ raw) {
    __shared__ int bad;
    int t = threadIdx.x;
    if (t == 0) bad = 0;
    __syncthreads();
    if (t < 64) {
        long long v = ((const long long*)raw)[t];
        if (v < 0 || v >= N_) atomicOr(&bad, 1);
    }
    __syncthreads();
    if (t < B_) g_vl[t] = bad ? ((const int*)raw)[t] : (int)((const long long*)raw)[t];
    for (int i = t; i < B_ * W_; i += blockDim.x) g_vsuf[i] = 0.f;
}

// ---- W^T hi/lo tiles ----
__global__ __launch_bounds__(128)
void prep_wt_kernel(const float* __restrict__ Wq, const float* __restrict__ Wk,
                    const float* __restrict__ Wv) {
    const float* W = (blockIdx.x == 0) ? Wq : (blockIdx.x == 1) ? Wk : Wv;
    int w = threadIdx.x;
    size_t base = (size_t)blockIdx.x * TILE_U32;
    for (int c = 0; c < 128; c += 2) {
        uint32_t h, l;
        split_pack(W[c * 128 + w], W[(c + 1) * 128 + w], h, l);
        g_wth[base + w * 64 + (c >> 1)] = h;
        g_wtl[base + w * 64 + (c >> 1)] = l;
    }
}

// ===========================================================================
// QKV: one block per 128-token tile, 256 threads (8 warps), warp tile 16x128.
// q,k stored K-major hi/lo; v stored TRANSPOSED (VT[w][m]) hi/lo; vsuf folded.
// ===========================================================================
#define QKV_SMEM ((4 * PT_U32 + 128) * 4)
__global__ __launch_bounds__(256)
void qkv_kernel(const float* __restrict__ x, const float* __restrict__ bq,
                const float* __restrict__ bk, const float* __restrict__ bv) {
    extern __shared__ uint32_t smu[];
    uint32_t* XH = smu;
    uint32_t* XL = smu + PT_U32;
    uint32_t* WH = smu + 2 * PT_U32;
    uint32_t* WL = smu + 3 * PT_U32;
    float* svs = (float*)(smu + 4 * PT_U32);

    int tid = threadIdx.x, warp = tid >> 5, lane = tid & 31;
    int g = lane >> 2, t = lane & 3, r0 = warp * 16;
    int blk = blockIdx.x, b = blk >> 2, tile = blk & 3;
    int vl = g_vl[b];
    bool kept = (tile * 128) <= vl;
    bool anymask = (tile * 128 + 127) > vl;

    // stage x (split hi/lo into padded SMEM)
    {
        const float4* xg = (const float4*)(x + (size_t)blk * 128 * C_);
        for (int i = tid; i < 4096; i += 256) {
            int r = i >> 5, c = (i & 31) << 2;
            float4 v = xg[i];
            uint32_t h0, l0, h1, l1;
            split_pack(v.x, v.y, h0, l0);
            split_pack(v.z, v.w, h1, l1);
            int o = r * PROW + (c >> 1);
            XH[o] = h0; XH[o + 1] = h1;
            XL[o] = l0; XL[o + 1] = l1;
        }
        if (tid < 128) svs[tid] = 0.f;
    }

#pragma unroll 1
    for (int mat = 0; mat < 3; mat++) {
        if (mat == 1 && !kept) continue;  // K tile never read
        __syncthreads();
        copy_pad(WH, g_wth + (size_t)mat * TILE_U32, tid);
        copy_pad(WL, g_wtl + (size_t)mat * TILE_U32, tid);
        __syncthreads();

        float acc[16][4];
#pragma unroll
        for (int nt = 0; nt < 16; nt++)
#pragma unroll
            for (int i = 0; i < 4; i++) acc[nt][i] = 0.f;

#pragma unroll
        for (int s = 0; s < 8; s++) {
            int ab = (r0 + g) * PROW + 8 * s + t;
            uint32_t ah0 = XH[ab], ah1 = XH[ab + 8 * PROW];
            uint32_t ah2 = XH[ab + 4], ah3 = XH[ab + 8 * PROW + 4];
            uint32_t al0 = XL[ab], al1 = XL[ab + 8 * PROW];
            uint32_t al2 = XL[ab + 4], al3 = XL[ab + 8 * PROW + 4];
#pragma unroll
            for (int nt = 0; nt < 16; nt++) {
                int bb = (8 * nt + g) * PROW + 8 * s + t;
                uint32_t bh0 = WH[bb], bh1 = WH[bb + 4];
                uint32_t bl0 = WL[bb], bl1 = WL[bb + 4];
                mma16816(acc[nt], ah0, ah1, ah2, ah3, bh0, bh1);
                mma16816(acc[nt], ah0, ah1, ah2, ah3, bl0, bl1);
                mma16816(acc[nt], al0, al1, al2, al3, bh0, bh1);
            }
        }

        const float* bias = (mat == 0) ? bq : (mat == 1) ? bk : bv;
        if (mat < 2) {
            uint32_t* dh = (mat == 0) ? g_qh : g_kh;
            uint32_t* dl = (mat == 0) ? g_ql : g_kl;
            size_t rg = (size_t)blk * 128 + r0 + g;
#pragma unroll
            for (int nt = 0; nt < 16; nt++) {
                int col = 8 * nt + 2 * t;
                float b0 = __ldg(bias + col), b1 = __ldg(bias + col + 1);
                uint32_t h, l;
                split_pack(acc[nt][0] + b0, acc[nt][1] + b1, h, l);
                dh[rg * 64 + 4 * nt + t] = h;
                dl[rg * 64 + 4 * nt + t] = l;
                split_pack(acc[nt][2] + b0, acc[nt][3] + b1, h, l);
                dh[(rg + 8) * 64 + 4 * nt + t] = h;
                dl[(rg + 8) * 64 + 4 * nt + t] = l;
            }
        } else {
            // V: vsuf (masked rows) + transpose into XH/XL staging -> g_vt
            __syncthreads();  // all warps done reading XH/XL as mma operands
            unsigned short* VTH = (unsigned short*)XH;
            unsigned short* VTL = (unsigned short*)XL;
            int nl0 = tile * 128 + r0 + g, nl1 = nl0 + 8;
#pragma unroll
            for (int nt = 0; nt < 16; nt++) {
                int col = 8 * nt + 2 * t;
                float b0 = __ldg(bias + col), b1 = __ldg(bias + col + 1);
                float f0 = acc[nt][0] + b0, f1 = acc[nt][1] + b1;
                float f2 = acc[nt][2] + b0, f3 = acc[nt][3] + b1;
                if (anymask) {
                    if (nl0 > vl) { atomicAdd(&svs[col], f0); atomicAdd(&svs[col + 1], f1); }
                    if (nl1 > vl) { atomicAdd(&svs[col], f2); atomicAdd(&svs[col + 1], f3); }
                }
                if (kept) {
                    unsigned short h, l;
                    split1(f0, h, l); VTH[col * 136 + r0 + g] = h;       VTL[col * 136 + r0 + g] = l;
                    split1(f1, h, l); VTH[(col + 1) * 136 + r0 + g] = h; VTL[(col + 1) * 136 + r0 + g] = l;
                    split1(f2, h, l); VTH[col * 136 + r0 + g + 8] = h;   VTL[col * 136 + r0 + g + 8] = l;
                    split1(f3, h, l); VTH[(col + 1) * 136 + r0 + g + 8] = h; VTL[(col + 1) * 136 + r0 + g + 8] = l;
                }
            }
            __syncthreads();
            if (kept) {  // padded staging -> unpadded global
                float4* d4h = (float4*)(g_vth + (size_t)blk * TILE_U32);
                float4* d4l = (float4*)(g_vtl + (size_t)blk * TILE_U32);
                const float4* s4h = (const float4*)XH;
                const float4* s4l = (const float4*)XL;
#pragma unroll
                for (int i = tid; i < 2048; i += 256) {
                    int r = i >> 4, q = i & 15;
                    d4h[i] = s4h[r * 17 + q];
                    d4l[i] = s4l[r * 17 + q];
                }
            }
            if (anymask && tid < 128) atomicAdd(&g_vsuf[b * 128 + tid], svs[tid]);
        }
    }
}

// ===========================================================================
// Attention: one block per (batch, 128-row q tile), 256 threads.
// S = Q@K^T (3-term mma.sync), exp in regs (no max), P stays in registers
// (C-fragment -> A-fragment repack), O += P@VT^T, analytic mask fold.
// ===========================================================================
#define ATTN_SMEM (6 * PT_U32 * 4)
__global__ __launch_bounds__(256)
void attn_kernel(float* __restrict__ out) {
    extern __shared__ uint32_t smu[];
    uint32_t* QH = smu;
    uint32_t* QL = smu + PT_U32;
    uint32_t* KH = smu + 2 * PT_U32;
    uint32_t* KL = smu + 3 * PT_U32;
    uint32_t* VTH = smu + 4 * PT_U32;
    uint32_t* VTL = smu + 5 * PT_U32;

    int tid = threadIdx.x, warp = tid >> 5, lane = tid & 31;
    int g = lane >> 2, t = lane & 3, r0 = warp * 16;
    int b = blockIdx.x, qt = blockIdx.y;
    int vl = g_vl[b];
    int nchunk = (vl >> 7) + 1;

    copy_pad(QH, g_qh + (size_t)(b * 4 + qt) * TILE_U32, tid);
    copy_pad(QL, g_ql + (size_t)(b * 4 + qt) * TILE_U32, tid);

    float oacc[16][4];
#pragma unroll
    for (int nt = 0; nt < 16; nt++)
#pragma unroll
        for (int i = 0; i < 4; i++) oacc[nt][i] = 0.f;
    float ps0 = 0.f, ps1 = 0.f;

#pragma unroll 1
    for (int c = 0; c < nchunk; c++) {
        __syncthreads();  // prev AV done (and Q copy for c==0)
        size_t kb = (size_t)(b * 4 + c) * TILE_U32;
        copy_pad(KH, g_kh + kb, tid);
        copy_pad(KL, g_kl + kb, tid);
        copy_pad(VTH, g_vth + kb, tid);
        copy_pad(VTL, g_vtl + kb, tid);
        __syncthreads();

        // ---- S = Q @ K^T (3-term) ----
        float sacc[16][4];
#pragma unroll
        for (int nt = 0; nt < 16; nt++)
#pragma unroll
            for (int i = 0; i < 4; i++) sacc[nt][i] = 0.f;
#pragma unroll
        for (int s = 0; s < 8; s++) {
            int ab = (r0 + g) * PROW + 8 * s + t;
            uint32_t ah0 = QH[ab], ah1 = QH[ab + 8 * PROW];
            uint32_t ah2 = QH[ab + 4], ah3 = QH[ab + 8 * PROW + 4];
            uint32_t al0 = QL[ab], al1 = QL[ab + 8 * PROW];
            uint32_t al2 = QL[ab + 4], al3 = QL[ab + 8 * PROW + 4];
#pragma unroll
            for (int nt = 0; nt < 16; nt++) {
                int bb = (8 * nt + g) * PROW + 8 * s + t;
                uint32_t bh0 = KH[bb], bh1 = KH[bb + 4];
                uint32_t bl0 = KL[bb], bl1 = KL[bb + 4];
                mma16816(sacc[nt], ah0, ah1, ah2, ah3, bh0, bh1);
                mma16816(sacc[nt], ah0, ah1, ah2, ah3, bl0, bl1);
                mma16816(sacc[nt], al0, al1, al2, al3, bh0, bh1);
            }
        }

        // ---- masked exp (no max subtraction), in place ----
#pragma unroll
        for (int nt = 0; nt < 16; nt++) {
            int n0 = c * 128 + 8 * nt + 2 * t;
            float e0 = (n0 <= vl) ? __expf(sacc[nt][0]) : 0.f;
            float e1 = (n0 + 1 <= vl) ? __expf(sacc[nt][1]) : 0.f;
            float e2 = (n0 <= vl) ? __expf(sacc[nt][2]) : 0.f;
            float e3 = (n0 + 1 <= vl) ? __expf(sacc[nt][3]) : 0.f;
            ps0 += e0 + e1;
            ps1 += e2 + e3;
            sacc[nt][0] = e0; sacc[nt][1] = e1;
            sacc[nt][2] = e2; sacc[nt][3] = e3;
        }

        // ---- O += P @ VT^T (P from registers: C-frag -> A-frag repack) ----
#pragma unroll
        for (int s = 0; s < 8; s++) {
            uint32_t ph0, pl0, ph1, pl1, ph2, pl2, ph3, pl3;
            split_pack(sacc[2 * s][0], sacc[2 * s][1], ph0, pl0);
            split_pack(sacc[2 * s][2], sacc[2 * s][3], ph1, pl1);
            split_pack(sacc[2 * s + 1][0], sacc[2 * s + 1][1], ph2, pl2);
            split_pack(sacc[2 * s + 1][2], sacc[2 * s + 1][3], ph3, pl3);
#pragma unroll
            for (int nt = 0; nt < 16; nt++) {
                int bb = (8 * nt + g) * PROW + 8 * s + t;
                uint32_t vh0 = VTH[bb], vh1 = VTH[bb + 4];
                uint32_t vl0 = VTL[bb], vl1 = VTL[bb + 4];
                mma16816(oacc[nt], ph0, ph1, ph2, ph3, vh0, vh1);
                mma16816(oacc[nt], ph0, ph1, ph2, ph3, vl0, vl1);
                mma16816(oacc[nt], pl0, pl1, pl2, pl3, vh0, vh1);
            }
        }
    }

    // ---- row sums (quad reduce) + epilogue ----
    ps0 += __shfl_xor_sync(0xffffffffu, ps0, 1);
    ps0 += __shfl_xor_sync(0xffffffffu, ps0, 2);
    ps1 += __shfl_xor_sync(0xffffffffu, ps1, 1);
    ps1 += __shfl_xor_sync(0xffffffffu, ps1, 2);
    float wm = __expf(MASKF);
    float nm = (float)(N_ - 1 - vl) * wm;
    float rt0 = 1.f / (ps0 + nm);
    float rt1 = 1.f / (ps1 + nm);
    const float* vs = g_vsuf + b * 128;
    size_t rg = (size_t)b * N_ + qt * 128 + r0 + g;
#pragma unroll
    for (int nt = 0; nt < 16; nt++) {
        int col = 8 * nt + 2 * t;
        float v0 = __ldg(vs + col), v1 = __ldg(vs + col + 1);
        float2 o0 = make_float2((oacc[nt][0] + wm * v0) * rt0,
                                (oacc[nt][1] + wm * v1) * rt0);
        float2 o1 = make_float2((oacc[nt][2] + wm * v0) * rt1,
                                (oacc[nt][3] + wm * v1) * rt1);
        *(float2*)(out + rg * 128 + col) = o0;
        *(float2*)(out + (rg + 8) * 128 + col) = o1;
    }
}

// ---- launch ----
extern "C" void kernel_launch(void* const* d_in, const int* in_sizes, int n_in,
                              void* d_out, int out_size) {
    const float* x  = (const float*)d_in[0];
    const float* Wq = (const float*)d_in[1];
    const float* bq = (const float*)d_in[2];
    const float* Wk = (const float*)d_in[3];
    const float* bk = (const float*)d_in[4];
    const float* Wv = (const float*)d_in[5];
    const float* bv = (const float*)d_in[6];
    const void*  vl = d_in[7];

    cudaFuncSetAttribute(qkv_kernel, cudaFuncAttributeMaxDynamicSharedMemorySize, QKV_SMEM);
    cudaFuncSetAttribute(attn_kernel, cudaFuncAttributeMaxDynamicSharedMemorySize, ATTN_SMEM);

    decode_vl_kernel<<<1, 128>>>(vl);
    prep_wt_kernel<<<3, 128>>>(Wq, Wk, Wv);
    qkv_kernel<<<B_ * 4, 256, QKV_SMEM>>>(x, bq, bk, bv);
    attn_kernel<<<dim3(B_, 4), 256, ATTN_SMEM>>>((float*)d_out);
}

// round 9
// speedup vs baseline: 2.6976x; 1.5684x over previous
#include <cuda_runtime.h>
#include <cuda_bf16.h>
#include <cstdint>

#define B_ 128
#define N_ 512
#define MASKF (-1e-6f)

#define TILE_U32 8192        // 128x128 bf16 tile = 128 rows x 64 u32 (unpadded)
#define PROW 68              // padded SMEM row stride (u32) = 272B
#define PT_U32 (128 * PROW)  // padded tile u32 count

// ---- global scratch (static: allocation-free) ----
__device__ __align__(16) uint32_t g_xh[(size_t)B_ * 4 * TILE_U32];
__device__ __align__(16) uint32_t g_xl[(size_t)B_ * 4 * TILE_U32];
__device__ __align__(16) uint32_t g_qh[(size_t)B_ * 4 * TILE_U32];
__device__ __align__(16) uint32_t g_ql[(size_t)B_ * 4 * TILE_U32];
__device__ __align__(16) uint32_t g_kh[(size_t)B_ * 4 * TILE_U32];
__device__ __align__(16) uint32_t g_kl[(size_t)B_ * 4 * TILE_U32];
__device__ __align__(16) uint32_t g_vvh[(size_t)B_ * 4 * TILE_U32];  // V K-major
__device__ __align__(16) uint32_t g_vvl[(size_t)B_ * 4 * TILE_U32];
__device__ __align__(16) uint32_t g_wth[3 * TILE_U32];  // W^T hi (q,k,v)
__device__ __align__(16) uint32_t g_wtl[3 * TILE_U32];
__device__ float g_vsuf[B_ * 128];
__device__ int   g_vl[B_];

// ---- helpers ----
__device__ __forceinline__ uint32_t smem_u32(const void* p) {
    uint32_t a;
    asm("{ .reg .u64 t; cvta.to.shared.u64 t, %1; cvt.u32.u64 %0, t; }" : "=r"(a) : "l"(p));
    return a;
}
// fast two-term bf16 split of a float pair: h = [bf(f1)|bf(f0)], l = residuals
__device__ __forceinline__ void split_pack(float f0, float f1,
                                           uint32_t& h, uint32_t& l) {
    asm("cvt.rn.bf16x2.f32 %0, %1, %2;" : "=r"(h) : "f"(f1), "f"(f0));
    float hf0 = __uint_as_float(h << 16);
    float hf1 = __uint_as_float(h & 0xffff0000u);
    float l0 = f0 - hf0, l1 = f1 - hf1;
    asm("cvt.rn.bf16x2.f32 %0, %1, %2;" : "=r"(l) : "f"(l1), "f"(l0));
}
__device__ __forceinline__ void mma16816(float c[4], uint32_t a0, uint32_t a1,
                                         uint32_t a2, uint32_t a3,
                                         uint32_t b0, uint32_t b1) {
    asm volatile(
        "mma.sync.aligned.m16n8k16.row.col.f32.bf16.bf16.f32 "
        "{%0,%1,%2,%3}, {%4,%5,%6,%7}, {%8,%9}, {%0,%1,%2,%3};"
        : "+f"(c[0]), "+f"(c[1]), "+f"(c[2]), "+f"(c[3])
        : "r"(a0), "r"(a1), "r"(a2), "r"(a3), "r"(b0), "r"(b1));
}
__device__ __forceinline__ void mma3x(float c[4], const uint32_t ah[4],
                                      const uint32_t al[4],
                                      uint32_t bh0, uint32_t bh1,
                                      uint32_t bl0, uint32_t bl1) {
    mma16816(c, ah[0], ah[1], ah[2], ah[3], bh0, bh1);
    mma16816(c, ah[0], ah[1], ah[2], ah[3], bl0, bl1);
    mma16816(c, al[0], al[1], al[2], al[3], bh0, bh1);
}
#define LDSM4(R, a)                                                            \
    asm volatile("ldmatrix.sync.aligned.m8n8.x4.shared.b16 {%0,%1,%2,%3}, [%4];" \
        : "=r"((R)[0]), "=r"((R)[1]), "=r"((R)[2]), "=r"((R)[3]) : "r"(a))
#define LDSM4T(R, a)                                                           \
    asm volatile("ldmatrix.sync.aligned.m8n8.x4.trans.shared.b16 {%0,%1,%2,%3}, [%4];" \
        : "=r"((R)[0]), "=r"((R)[1]), "=r"((R)[2]), "=r"((R)[3]) : "r"(a))
#define CP16(saddr, gptr)                                                      \
    asm volatile("cp.async.cg.shared.global [%0], [%1], 16;" :: "r"(saddr), "l"(gptr))
#define CP_COMMIT() asm volatile("cp.async.commit_group;" ::: "memory")
#define CP_WAIT(n)  asm volatile("cp.async.wait_group %0;" :: "n"(n) : "memory")

// cp.async one unpadded 32KB tile -> padded smem (stride 17 float4/row-of-16)
__device__ __forceinline__ void cpa_tile(uint32_t dst_byte, const uint32_t* src, int tid) {
    const float4* s4 = (const float4*)src;
#pragma unroll
    for (int i = tid; i < 2048; i += 256)
        CP16(dst_byte + ((i >> 4) * 17 + (i & 15)) * 16, s4 + i);
}
// degree-6 exp2 polynomial exp (FFMA pipe); valid for |x| <~ 80
__device__ __forceinline__ float exp_poly(float x) {
    float y = x * 1.4426950408889634f;
    int ni = __float2int_rn(y);
    float f = y - __int2float_rn(ni);
    float p = 1.54035e-4f;
    p = fmaf(p, f, 1.33336e-3f);
    p = fmaf(p, f, 9.61813e-3f);
    p = fmaf(p, f, 5.55041e-2f);
    p = fmaf(p, f, 2.402265e-1f);
    p = fmaf(p, f, 6.931472e-1f);
    p = fmaf(p, f, 1.0f);
    return __int_as_float(__float_as_int(p) + (ni << 23));
}

// ---- decode valid_len (runtime int64-vs-int32 detect) ----
__global__ void decode_vl_kernel(const void* __restrict__ raw) {
    __shared__ int bad;
    int t = threadIdx.x;
    if (t == 0) bad = 0;
    __syncthreads();
    if (t < 64) {
        long long v = ((const long long*)raw)[t];
        if (v < 0 || v >= N_) atomicOr(&bad, 1);
    }
    __syncthreads();
    if (t < B_) g_vl[t] = bad ? ((const int*)raw)[t] : (int)((const long long*)raw)[t];
}

// ---- W^T hi/lo tiles (row = out col w, col = c) ----
__global__ __launch_bounds__(128)
void prep_wt_kernel(const float* __restrict__ Wq, const float* __restrict__ Wk,
                    const float* __restrict__ Wv) {
    const float* W = (blockIdx.x == 0) ? Wq : (blockIdx.x == 1) ? Wk : Wv;
    int w = threadIdx.x;
    size_t base = (size_t)blockIdx.x * TILE_U32;
    for (int c = 0; c < 128; c += 2) {
        uint32_t h, l;
        split_pack(W[c * 128 + w], W[(c + 1) * 128 + w], h, l);
        g_wth[base + w * 64 + (c >> 1)] = h;
        g_wtl[base + w * 64 + (c >> 1)] = l;
    }
}

// ---- x split hi/lo (once) ----
__global__ __launch_bounds__(256)
void prep_x_kernel(const float* __restrict__ x) {
    int blk = blockIdx.x, tid = threadIdx.x;
    const float4* xg = (const float4*)(x + (size_t)blk * 128 * 128);
    uint2* dh = (uint2*)(g_xh + (size_t)blk * TILE_U32);
    uint2* dl = (uint2*)(g_xl + (size_t)blk * TILE_U32);
#pragma unroll
    for (int i = tid; i < 4096; i += 256) {
        float4 v = xg[i];
        uint32_t h0, l0, h1, l1;
        split_pack(v.x, v.y, h0, l0);
        split_pack(v.z, v.w, h1, l1);
        dh[i] = make_uint2(h0, h1);
        dl[i] = make_uint2(l0, l1);
    }
}

// ---- vsuf[b][w] = (sum_{m>vl} x[b,m,:]) @ Wv + cnt*bv  (exact fp32) ----
__global__ __launch_bounds__(128)
void vsuf_kernel(const float* __restrict__ x, const float* __restrict__ Wv,
                 const float* __restrict__ bv) {
    __shared__ float xs[128];
    int b = blockIdx.x, tid = threadIdx.x;
    int vl = g_vl[b];
    float s = 0.f;
    for (int m = vl + 1; m < N_; m++) s += x[((size_t)b * N_ + m) * 128 + tid];
    xs[tid] = s;
    __syncthreads();
    float acc = (float)(N_ - 1 - vl) * bv[tid];
    for (int c = 0; c < 128; c++) acc = fmaf(xs[c], Wv[c * 128 + tid], acc);
    g_vsuf[b * 128 + tid] = acc;
}

// ===========================================================================
// QKV: grid (512, 3). One block per (token-tile, matrix). 3-term bf16 GEMM.
// K/V tiles skipped when fully masked. V stored K-major (no transpose).
// ===========================================================================
#define QKV_SMEM (16 * PT_U32)
__global__ __launch_bounds__(256)
void qkv_kernel(const float* __restrict__ bq, const float* __restrict__ bk,
                const float* __restrict__ bv) {
    extern __shared__ uint32_t smu[];
    int tid = threadIdx.x, warp = tid >> 5, lane = tid & 31;
    int g = lane >> 2, t = lane & 3, r0 = warp * 16;
    int blk = blockIdx.x, mat = blockIdx.y;
    int b = blk >> 2, tile = blk & 3, vl = g_vl[b];
    if (mat && tile * 128 > vl) return;

    uint32_t smb = smem_u32(smu);
    cpa_tile(smb, g_xh + (size_t)blk * TILE_U32, tid);
    cpa_tile(smb + 4 * PT_U32, g_xl + (size_t)blk * TILE_U32, tid);
    cpa_tile(smb + 8 * PT_U32, g_wth + (size_t)mat * TILE_U32, tid);
    cpa_tile(smb + 12 * PT_U32, g_wtl + (size_t)mat * TILE_U32, tid);
    CP_COMMIT();
    CP_WAIT(0);
    __syncthreads();

    float sacc[16][4];
#pragma unroll
    for (int nt = 0; nt < 16; nt++)
#pragma unroll
        for (int i = 0; i < 4; i++) sacc[nt][i] = 0.f;

    uint32_t a_base = smb + 4 * ((r0 + (lane & 15)) * PROW + ((lane & 16) >> 2));
    uint32_t b_base = smb + 8 * PT_U32 +
                      4 * (((lane & 7) + ((lane & 16) >> 1)) * PROW + ((lane & 8) >> 1));
#pragma unroll 1
    for (int s = 0; s < 8; s++) {
        uint32_t ah[4], al[4];
        LDSM4(ah, a_base + 32 * s);
        LDSM4(al, a_base + 4 * PT_U32 + 32 * s);
#pragma unroll
        for (int p = 0; p < 8; p++) {
            uint32_t bh[4], bl[4];
            LDSM4(bh, b_base + 4352 * p + 32 * s);
            LDSM4(bl, b_base + 4 * PT_U32 + 4352 * p + 32 * s);
            mma3x(sacc[2 * p], ah, al, bh[0], bh[1], bl[0], bl[1]);
            mma3x(sacc[2 * p + 1], ah, al, bh[2], bh[3], bl[2], bl[3]);
        }
    }

    const float* bias = (mat == 0) ? bq : (mat == 1) ? bk : bv;
    uint32_t* dh = (mat == 0) ? g_qh : (mat == 1) ? g_kh : g_vvh;
    uint32_t* dl = (mat == 0) ? g_ql : (mat == 1) ? g_kl : g_vvl;
    size_t rg = (size_t)blk * 128 + r0 + g;
#pragma unroll
    for (int nt = 0; nt < 16; nt++) {
        int col = 8 * nt + 2 * t;
        float b0 = __ldg(bias + col), b1 = __ldg(bias + col + 1);
        uint32_t h, l;
        split_pack(sacc[nt][0] + b0, sacc[nt][1] + b1, h, l);
        dh[rg * 64 + 4 * nt + t] = h;
        dl[rg * 64 + 4 * nt + t] = l;
        split_pack(sacc[nt][2] + b0, sacc[nt][3] + b1, h, l);
        dh[(rg + 8) * 64 + 4 * nt + t] = h;
        dl[(rg + 8) * 64 + 4 * nt + t] = l;
    }
}

// ===========================================================================
// Attention: grid (128, 4). ldmatrix fragments, hybrid exp, cp.async overlap.
// ===========================================================================
#define ATTN_SMEM (24 * PT_U32)
__global__ __launch_bounds__(256)
void attn_kernel(float* __restrict__ out) {
    extern __shared__ uint32_t smu[];
    int tid = threadIdx.x, warp = tid >> 5, lane = tid & 31;
    int g = lane >> 2, t = lane & 3, r0 = warp * 16;
    int b = blockIdx.x, qt = blockIdx.y;
    int vl = g_vl[b], nchunk = (vl >> 7) + 1;
    uint32_t smb = smem_u32(smu);

    size_t qb = (size_t)(b * 4 + qt) * TILE_U32;
    cpa_tile(smb, g_qh + qb, tid);
    cpa_tile(smb + 4 * PT_U32, g_ql + qb, tid);
    CP_COMMIT();
    size_t kb0 = (size_t)(b * 4) * TILE_U32;
    cpa_tile(smb + 8 * PT_U32, g_kh + kb0, tid);
    cpa_tile(smb + 12 * PT_U32, g_kl + kb0, tid);
    CP_COMMIT();
    cpa_tile(smb + 16 * PT_U32, g_vvh + kb0, tid);
    cpa_tile(smb + 20 * PT_U32, g_vvl + kb0, tid);
    CP_COMMIT();

    uint32_t qa = smb + 4 * ((r0 + (lane & 15)) * PROW + ((lane & 16) >> 2));
    uint32_t kbb = smb + 8 * PT_U32 +
                   4 * (((lane & 7) + ((lane & 16) >> 1)) * PROW + ((lane & 8) >> 1));
    uint32_t vbb = smb + 16 * PT_U32 +
                   4 * (((lane & 7) + (lane & 8)) * PROW + ((lane & 16) >> 2));

    float oacc[16][4];
#pragma unroll
    for (int nt = 0; nt < 16; nt++)
#pragma unroll
        for (int i = 0; i < 4; i++) oacc[nt][i] = 0.f;
    float ps0 = 0.f, ps1 = 0.f;

#pragma unroll 1
    for (int c = 0; c < nchunk; c++) {
        CP_WAIT(1);          // Q+K ready (V may still be in flight)
        __syncthreads();

        // ---- S = Q @ K^T ----
        float sacc[16][4];
#pragma unroll
        for (int nt = 0; nt < 16; nt++)
#pragma unroll
            for (int i = 0; i < 4; i++) sacc[nt][i] = 0.f;
#pragma unroll 1
        for (int s = 0; s < 8; s++) {
            uint32_t ah[4], al[4];
            LDSM4(ah, qa + 32 * s);
            LDSM4(al, qa + 4 * PT_U32 + 32 * s);
#pragma unroll
            for (int p = 0; p < 8; p++) {
                uint32_t bh[4], bl[4];
                LDSM4(bh, kbb + 4352 * p + 32 * s);
                LDSM4(bl, kbb + 4 * PT_U32 + 4352 * p + 32 * s);
                mma3x(sacc[2 * p], ah, al, bh[0], bh[1], bl[0], bl[1]);
                mma3x(sacc[2 * p + 1], ah, al, bh[2], bh[3], bl[2], bl[3]);
            }
        }

        // ---- masked exp (no max subtraction), hybrid MUFU/FFMA ----
        int cn = c * 128 + 2 * t;
#pragma unroll
        for (int nt = 0; nt < 16; nt++) {
            int n0 = cn + 8 * nt;
            float e0, e1, e2, e3;
            if (nt & 1) {
                e0 = exp_poly(sacc[nt][0]); e1 = exp_poly(sacc[nt][1]);
                e2 = exp_poly(sacc[nt][2]); e3 = exp_poly(sacc[nt][3]);
            } else {
                e0 = __expf(sacc[nt][0]); e1 = __expf(sacc[nt][1]);
                e2 = __expf(sacc[nt][2]); e3 = __expf(sacc[nt][3]);
            }
            e0 = (n0 <= vl) ? e0 : 0.f;
            e1 = (n0 + 1 <= vl) ? e1 : 0.f;
            e2 = (n0 <= vl) ? e2 : 0.f;
            e3 = (n0 + 1 <= vl) ? e3 : 0.f;
            ps0 += e0 + e1;
            ps1 += e2 + e3;
            sacc[nt][0] = e0; sacc[nt][1] = e1;
            sacc[nt][2] = e2; sacc[nt][3] = e3;
        }

        CP_WAIT(0);          // V ready
        __syncthreads();

        // ---- O += P @ V (P regs -> A-frags; V via ldmatrix.trans) ----
#pragma unroll
        for (int s = 0; s < 8; s++) {
            uint32_t ph0, pl0, ph1, pl1, ph2, pl2, ph3, pl3;
            split_pack(sacc[2 * s][0], sacc[2 * s][1], ph0, pl0);
            split_pack(sacc[2 * s][2], sacc[2 * s][3], ph1, pl1);
            split_pack(sacc[2 * s + 1][0], sacc[2 * s + 1][1], ph2, pl2);
            split_pack(sacc[2 * s + 1][2], sacc[2 * s + 1][3], ph3, pl3);
#pragma unroll
            for (int p = 0; p < 8; p++) {
                uint32_t vh[4], vo[4];
                LDSM4T(vh, vbb + 4352 * s + 32 * p);
                LDSM4T(vo, vbb + 4 * PT_U32 + 4352 * s + 32 * p);
                mma16816(oacc[2 * p], ph0, ph1, ph2, ph3, vh[0], vh[1]);
                mma16816(oacc[2 * p], ph0, ph1, ph2, ph3, vo[0], vo[1]);
                mma16816(oacc[2 * p], pl0, pl1, pl2, pl3, vh[0], vh[1]);
                mma16816(oacc[2 * p + 1], ph0, ph1, ph2, ph3, vh[2], vh[3]);
                mma16816(oacc[2 * p + 1], ph0, ph1, ph2, ph3, vo[2], vo[3]);
                mma16816(oacc[2 * p + 1], pl0, pl1, pl2, pl3, vh[2], vh[3]);
            }
        }

        if (c + 1 < nchunk) {   // prefetch next K/V chunk
            __syncthreads();    // all warps done with current K/V smem
            size_t nb = (size_t)(b * 4 + c + 1) * TILE_U32;
            cpa_tile(smb + 8 * PT_U32, g_kh + nb, tid);
            cpa_tile(smb + 12 * PT_U32, g_kl + nb, tid);
            CP_COMMIT();
            cpa_tile(smb + 16 * PT_U32, g_vvh + nb, tid);
            cpa_tile(smb + 20 * PT_U32, g_vvl + nb, tid);
            CP_COMMIT();
        }
    }

    // ---- row sums + epilogue with analytic mask fold ----
    ps0 += __shfl_xor_sync(0xffffffffu, ps0, 1);
    ps0 += __shfl_xor_sync(0xffffffffu, ps0, 2);
    ps1 += __shfl_xor_sync(0xffffffffu, ps1, 1);
    ps1 += __shfl_xor_sync(0xffffffffu, ps1, 2);
    float wm = __expf(MASKF);
    float nm = (float)(N_ - 1 - vl) * wm;
    float rt0 = 1.f / (ps0 + nm);
    float rt1 = 1.f / (ps1 + nm);
    const float* vs = g_vsuf + b * 128;
    size_t rg = (size_t)b * N_ + qt * 128 + r0 + g;
#pragma unroll
    for (int nt = 0; nt < 16; nt++) {
        int col = 8 * nt + 2 * t;
        float v0 = __ldg(vs + col), v1 = __ldg(vs + col + 1);
        float2 o0 = make_float2((oacc[nt][0] + wm * v0) * rt0,
                                (oacc[nt][1] + wm * v1) * rt0);
        float2 o1 = make_float2((oacc[nt][2] + wm * v0) * rt1,
                                (oacc[nt][3] + wm * v1) * rt1);
        *(float2*)(out + rg * 128 + col) = o0;
        *(float2*)(out + (rg + 8) * 128 + col) = o1;
    }
}

// ---- launch ----
extern "C" void kernel_launch(void* const* d_in, const int* in_sizes, int n_in,
                              void* d_out, int out_size) {
    const float* x  = (const float*)d_in[0];
    const float* Wq = (const float*)d_in[1];
    const float* bq = (const float*)d_in[2];
    const float* Wk = (const float*)d_in[3];
    const float* bk = (const float*)d_in[4];
    const float* Wv = (const float*)d_in[5];
    const float* bv = (const float*)d_in[6];
    const void*  vl = d_in[7];

    cudaFuncSetAttribute(qkv_kernel, cudaFuncAttributeMaxDynamicSharedMemorySize, QKV_SMEM);
    cudaFuncSetAttribute(attn_kernel, cudaFuncAttributeMaxDynamicSharedMemorySize, ATTN_SMEM);

    decode_vl_kernel<<<1, 128>>>(vl);
    prep_wt_kernel<<<3, 128>>>(Wq, Wk, Wv);
    prep_x_kernel<<<B_ * 4, 256>>>(x);
    vsuf_kernel<<<B_, 128>>>(x, Wv, bv);
    qkv_kernel<<<dim3(B_ * 4, 3), 256, QKV_SMEM>>>(bq, bk, bv);
    attn_kernel<<<dim3(B_, 4), 256, ATTN_SMEM>>>((float*)d_out);
}

// round 11
// speedup vs baseline: 2.7453x; 1.0177x over previous
#include <cuda_runtime.h>
#include <cuda_bf16.h>
#include <cstdint>

#define B_ 128
#define N_ 512
#define MASKF (-1e-6f)

#define TILE_U32 8192        // 128x128 bf16 tile = 128 rows x 64 u32 (unpadded)
#define PROW 68              // padded SMEM row stride (u32) = 272B
#define PT_U32 (128 * PROW)  // padded tile u32 count

// ---- global scratch (static: allocation-free) ----
__device__ __align__(16) uint32_t g_xh[(size_t)B_ * 4 * TILE_U32];
__device__ __align__(16) uint32_t g_xl[(size_t)B_ * 4 * TILE_U32];
__device__ __align__(16) uint32_t g_qh[(size_t)B_ * 4 * TILE_U32];
__device__ __align__(16) uint32_t g_ql[(size_t)B_ * 4 * TILE_U32];
__device__ __align__(16) uint32_t g_kh[(size_t)B_ * 4 * TILE_U32];
__device__ __align__(16) uint32_t g_kl[(size_t)B_ * 4 * TILE_U32];
__device__ __align__(16) uint32_t g_vvh[(size_t)B_ * 4 * TILE_U32];  // V K-major
__device__ __align__(16) uint32_t g_vvl[(size_t)B_ * 4 * TILE_U32];
__device__ __align__(16) uint32_t g_wth[3 * TILE_U32];  // W^T hi (q,k,v)
__device__ __align__(16) uint32_t g_wtl[3 * TILE_U32];
__device__ float g_xsum[B_ * 128];   // sum_{m>vl} x[b,m,c]
__device__ float g_vsuf[B_ * 128];
__device__ int   g_vl[B_];

// ---- helpers ----
__device__ __forceinline__ uint32_t smem_u32(const void* p) {
    uint32_t a;
    asm("{ .reg .u64 t; cvta.to.shared.u64 t, %1; cvt.u32.u64 %0, t; }" : "=r"(a) : "l"(p));
    return a;
}
// fast two-term bf16 split of a float pair: h = [bf(f1)|bf(f0)], l = residuals
__device__ __forceinline__ void split_pack(float f0, float f1,
                                           uint32_t& h, uint32_t& l) {
    asm("cvt.rn.bf16x2.f32 %0, %1, %2;" : "=r"(h) : "f"(f1), "f"(f0));
    float hf0 = __uint_as_float(h << 16);
    float hf1 = __uint_as_float(h & 0xffff0000u);
    float l0 = f0 - hf0, l1 = f1 - hf1;
    asm("cvt.rn.bf16x2.f32 %0, %1, %2;" : "=r"(l) : "f"(l1), "f"(l0));
}
__device__ __forceinline__ void mma16816(float c[4], uint32_t a0, uint32_t a1,
                                         uint32_t a2, uint32_t a3,
                                         uint32_t b0, uint32_t b1) {
    asm volatile(
        "mma.sync.aligned.m16n8k16.row.col.f32.bf16.bf16.f32 "
        "{%0,%1,%2,%3}, {%4,%5,%6,%7}, {%8,%9}, {%0,%1,%2,%3};"
        : "+f"(c[0]), "+f"(c[1]), "+f"(c[2]), "+f"(c[3])
        : "r"(a0), "r"(a1), "r"(a2), "r"(a3), "r"(b0), "r"(b1));
}
__device__ __forceinline__ void mma3x(float c[4], const uint32_t ah[4],
                                      const uint32_t al[4],
                                      uint32_t bh0, uint32_t bh1,
                                      uint32_t bl0, uint32_t bl1) {
    mma16816(c, ah[0], ah[1], ah[2], ah[3], bh0, bh1);
    mma16816(c, ah[0], ah[1], ah[2], ah[3], bl0, bl1);
    mma16816(c, al[0], al[1], al[2], al[3], bh0, bh1);
}
#define LDSM4(R, a)                                                            \
    asm volatile("ldmatrix.sync.aligned.m8n8.x4.shared.b16 {%0,%1,%2,%3}, [%4];" \
        : "=r"((R)[0]), "=r"((R)[1]), "=r"((R)[2]), "=r"((R)[3]) : "r"(a))
#define LDSM4T(R, a)                                                           \
    asm volatile("ldmatrix.sync.aligned.m8n8.x4.trans.shared.b16 {%0,%1,%2,%3}, [%4];" \
        : "=r"((R)[0]), "=r"((R)[1]), "=r"((R)[2]), "=r"((R)[3]) : "r"(a))
#define CP16(saddr, gptr)                                                      \
    asm volatile("cp.async.cg.shared.global [%0], [%1], 16;" :: "r"(saddr), "l"(gptr))
#define CP_COMMIT() asm volatile("cp.async.commit_group;" ::: "memory")
#define CP_WAIT(n)  asm volatile("cp.async.wait_group %0;" :: "n"(n) : "memory")

// cp.async one unpadded 32KB tile -> padded smem (stride 17 float4/row-of-16)
__device__ __forceinline__ void cpa_tile(uint32_t dst_byte, const uint32_t* src, int tid) {
    const float4* s4 = (const float4*)src;
#pragma unroll
    for (int i = tid; i < 2048; i += 256)
        CP16(dst_byte + ((i >> 4) * 17 + (i & 15)) * 16, s4 + i);
}
// degree-6 exp2 polynomial exp (FFMA pipe); valid for |x| <~ 80
__device__ __forceinline__ float exp_poly(float x) {
    float y = x * 1.4426950408889634f;
    int ni = __float2int_rn(y);
    float f = y - __int2float_rn(ni);
    float p = 1.54035e-4f;
    p = fmaf(p, f, 1.33336e-3f);
    p = fmaf(p, f, 9.61813e-3f);
    p = fmaf(p, f, 5.55041e-2f);
    p = fmaf(p, f, 2.402265e-1f);
    p = fmaf(p, f, 6.931472e-1f);
    p = fmaf(p, f, 1.0f);
    return __int_as_float(__float_as_int(p) + (ni << 23));
}

// ---- decode valid_len (runtime int64-vs-int32 detect) + zero xsum ----
__global__ __launch_bounds__(256)
void decode_vl_kernel(const void* __restrict__ raw) {
    __shared__ int bad;
    int t = threadIdx.x;
    if (t == 0) bad = 0;
    __syncthreads();
    if (t < 64) {
        long long v = ((const long long*)raw)[t];
        if (v < 0 || v >= N_) atomicOr(&bad, 1);
    }
    __syncthreads();
    if (t < B_) g_vl[t] = bad ? ((const int*)raw)[t] : (int)((const long long*)raw)[t];
    for (int i = t; i < B_ * 128; i += 256) g_xsum[i] = 0.f;
}

// ---- merged prep: blocks 0-2 do W^T hi/lo tiles; blocks 3.. split x ----
__global__ __launch_bounds__(256)
void prep_all_kernel(const float* __restrict__ x, const float* __restrict__ Wq,
                     const float* __restrict__ Wk, const float* __restrict__ Wv) {
    int blk = blockIdx.x, tid = threadIdx.x;
    if (blk < 3) {
        const float* W = (blk == 0) ? Wq : (blk == 1) ? Wk : Wv;
        int w = tid & 127;
        int c0 = (tid >> 7) * 64;  // two half-ranges of c per w
        size_t base = (size_t)blk * TILE_U32;
        for (int c = c0; c < c0 + 64; c += 2) {
            uint32_t h, l;
            split_pack(W[c * 128 + w], W[(c + 1) * 128 + w], h, l);
            g_wth[base + w * 64 + (c >> 1)] = h;
            g_wtl[base + w * 64 + (c >> 1)] = l;
        }
    } else {
        int xb = blk - 3;
        const float4* xg = (const float4*)(x + (size_t)xb * 128 * 128);
        uint2* dh = (uint2*)(g_xh + (size_t)xb * TILE_U32);
        uint2* dl = (uint2*)(g_xl + (size_t)xb * TILE_U32);
#pragma unroll
        for (int i = tid; i < 4096; i += 256) {
            float4 v = xg[i];
            uint32_t h0, l0, h1, l1;
            split_pack(v.x, v.y, h0, l0);
            split_pack(v.z, v.w, h1, l1);
            dh[i] = make_uint2(h0, h1);
            dl[i] = make_uint2(l0, l1);
        }
    }
}

// ---- xsum phase 1: per 128-row tile, accumulate masked-row sums ----
__global__ __launch_bounds__(128)
void xsum_kernel(const float* __restrict__ x) {
    int b = blockIdx.x, tile = blockIdx.y, tid = threadIdx.x;
    int vl = g_vl[b];
    int m0 = tile * 128, m1 = m0 + 128;
    int lo = (m0 > vl + 1) ? m0 : vl + 1;  // first masked row in this tile
    if (lo >= m1) return;                  // tile fully kept: no masked rows
    float s = 0.f;
    const float* xp = x + ((size_t)b * N_ + lo) * 128 + tid;
#pragma unroll 4
    for (int m = lo; m < m1; m++, xp += 128) s += *xp;
    atomicAdd(&g_xsum[b * 128 + tid], s);
}

// ---- vsuf phase 2: vsuf[b][w] = xsum[b]@Wv + cnt*bv (exact fp32 GEMV) ----
__global__ __launch_bounds__(128)
void vsuf_gemv_kernel(const float* __restrict__ Wv, const float* __restrict__ bv) {
    __shared__ float xs[128];
    int b = blockIdx.x, tid = threadIdx.x;
    int vl = g_vl[b];
    xs[tid] = g_xsum[b * 128 + tid];
    __syncthreads();
    float acc = (float)(N_ - 1 - vl) * bv[tid];
#pragma unroll 8
    for (int c = 0; c < 128; c++) acc = fmaf(xs[c], Wv[c * 128 + tid], acc);
    g_vsuf[b * 128 + tid] = acc;
}

// ===========================================================================
// QKV: grid (512, 3). One block per (token-tile, matrix). 3-term bf16 GEMM.
// K/V tiles skipped when fully masked. V stored K-major (no transpose).
// ===========================================================================
#define QKV_SMEM (16 * PT_U32)
__global__ __launch_bounds__(256)
void qkv_kernel(const float* __restrict__ bq, const float* __restrict__ bk,
                const float* __restrict__ bv) {
    extern __shared__ uint32_t smu[];
    int tid = threadIdx.x, warp = tid >> 5, lane = tid & 31;
    int g = lane >> 2, t = lane & 3, r0 = warp * 16;
    int blk = blockIdx.x, mat = blockIdx.y;
    int b = blk >> 2, tile = blk & 3, vl = g_vl[b];
    if (mat && tile * 128 > vl) return;

    uint32_t smb = smem_u32(smu);
    cpa_tile(smb, g_xh + (size_t)blk * TILE_U32, tid);
    cpa_tile(smb + 4 * PT_U32, g_xl + (size_t)blk * TILE_U32, tid);
    cpa_tile(smb + 8 * PT_U32, g_wth + (size_t)mat * TILE_U32, tid);
    cpa_tile(smb + 12 * PT_U32, g_wtl + (size_t)mat * TILE_U32, tid);
    CP_COMMIT();
    CP_WAIT(0);
    __syncthreads();

    float sacc[16][4];
#pragma unroll
    for (int nt = 0; nt < 16; nt++)
#pragma unroll
        for (int i = 0; i < 4; i++) sacc[nt][i] = 0.f;

    uint32_t a_base = smb + 4 * ((r0 + (lane & 15)) * PROW + ((lane & 16) >> 2));
    uint32_t b_base = smb + 8 * PT_U32 +
                      4 * (((lane & 7) + ((lane & 16) >> 1)) * PROW + ((lane & 8) >> 1));
#pragma unroll 1
    for (int s = 0; s < 8; s++) {
        uint32_t ah[4], al[4];
        LDSM4(ah, a_base + 32 * s);
        LDSM4(al, a_base + 4 * PT_U32 + 32 * s);
#pragma unroll
        for (int p = 0; p < 8; p++) {
            uint32_t bh[4], bl[4];
            LDSM4(bh, b_base + 4352 * p + 32 * s);
            LDSM4(bl, b_base + 4 * PT_U32 + 4352 * p + 32 * s);
            mma3x(sacc[2 * p], ah, al, bh[0], bh[1], bl[0], bl[1]);
            mma3x(sacc[2 * p + 1], ah, al, bh[2], bh[3], bl[2], bl[3]);
        }
    }

    const float* bias = (mat == 0) ? bq : (mat == 1) ? bk : bv;
    uint32_t* dh = (mat == 0) ? g_qh : (mat == 1) ? g_kh : g_vvh;
    uint32_t* dl = (mat == 0) ? g_ql : (mat == 1) ? g_kl : g_vvl;
    size_t rg = (size_t)blk * 128 + r0 + g;
#pragma unroll
    for (int nt = 0; nt < 16; nt++) {
        int col = 8 * nt + 2 * t;
        float b0 = __ldg(bias + col), b1 = __ldg(bias + col + 1);
        uint32_t h, l;
        split_pack(sacc[nt][0] + b0, sacc[nt][1] + b1, h, l);
        dh[rg * 64 + 4 * nt + t] = h;
        dl[rg * 64 + 4 * nt + t] = l;
        split_pack(sacc[nt][2] + b0, sacc[nt][3] + b1, h, l);
        dh[(rg + 8) * 64 + 4 * nt + t] = h;
        dl[(rg + 8) * 64 + 4 * nt + t] = l;
    }
}

// ===========================================================================
// Attention: grid (128, 4). ldmatrix fragments, hybrid exp, cp.async overlap.
// ===========================================================================
#define ATTN_SMEM (24 * PT_U32)
__global__ __launch_bounds__(256)
void attn_kernel(float* __restrict__ out) {
    extern __shared__ uint32_t smu[];
    int tid = threadIdx.x, warp = tid >> 5, lane = tid & 31;
    int g = lane >> 2, t = lane & 3, r0 = warp * 16;
    int b = blockIdx.x, qt = blockIdx.y;
    int vl = g_vl[b], nchunk = (vl >> 7) + 1;
    uint32_t smb = smem_u32(smu);

    size_t qb = (size_t)(b * 4 + qt) * TILE_U32;
    cpa_tile(smb, g_qh + qb, tid);
    cpa_tile(smb + 4 * PT_U32, g_ql + qb, tid);
    CP_COMMIT();
    size_t kb0 = (size_t)(b * 4) * TILE_U32;
    cpa_tile(smb + 8 * PT_U32, g_kh + kb0, tid);
    cpa_tile(smb + 12 * PT_U32, g_kl + kb0, tid);
    CP_COMMIT();
    cpa_tile(smb + 16 * PT_U32, g_vvh + kb0, tid);
    cpa_tile(smb + 20 * PT_U32, g_vvl + kb0, tid);
    CP_COMMIT();

    uint32_t qa = smb + 4 * ((r0 + (lane & 15)) * PROW + ((lane & 16) >> 2));
    uint32_t kbb = smb + 8 * PT_U32 +
                   4 * (((lane & 7) + ((lane & 16) >> 1)) * PROW + ((lane & 8) >> 1));
    uint32_t vbb = smb + 16 * PT_U32 +
                   4 * (((lane & 7) + (lane & 8)) * PROW + ((lane & 16) >> 2));

    float oacc[16][4];
#pragma unroll
    for (int nt = 0; nt < 16; nt++)
#pragma unroll
        for (int i = 0; i < 4; i++) oacc[nt][i] = 0.f;
    float ps0 = 0.f, ps1 = 0.f;

#pragma unroll 1
    for (int c = 0; c < nchunk; c++) {
        CP_WAIT(1);          // Q+K ready (V may still be in flight)
        __syncthreads();

        // ---- S = Q @ K^T ----
        float sacc[16][4];
#pragma unroll
        for (int nt = 0; nt < 16; nt++)
#pragma unroll
            for (int i = 0; i < 4; i++) sacc[nt][i] = 0.f;
#pragma unroll 1
        for (int s = 0; s < 8; s++) {
            uint32_t ah[4], al[4];
            LDSM4(ah, qa + 32 * s);
            LDSM4(al, qa + 4 * PT_U32 + 32 * s);
#pragma unroll
            for (int p = 0; p < 8; p++) {
                uint32_t bh[4], bl[4];
                LDSM4(bh, kbb + 4352 * p + 32 * s);
                LDSM4(bl, kbb + 4 * PT_U32 + 4352 * p + 32 * s);
                mma3x(sacc[2 * p], ah, al, bh[0], bh[1], bl[0], bl[1]);
                mma3x(sacc[2 * p + 1], ah, al, bh[2], bh[3], bl[2], bl[3]);
            }
        }

        // ---- masked exp (no max subtraction), hybrid MUFU/FFMA ----
        int cn = c * 128 + 2 * t;
#pragma unroll
        for (int nt = 0; nt < 16; nt++) {
            int n0 = cn + 8 * nt;
            float e0, e1, e2, e3;
            if (nt & 1) {
                e0 = exp_poly(sacc[nt][0]); e1 = exp_poly(sacc[nt][1]);
                e2 = exp_poly(sacc[nt][2]); e3 = exp_poly(sacc[nt][3]);
            } else {
                e0 = __expf(sacc[nt][0]); e1 = __expf(sacc[nt][1]);
                e2 = __expf(sacc[nt][2]); e3 = __expf(sacc[nt][3]);
            }
            e0 = (n0 <= vl) ? e0 : 0.f;
            e1 = (n0 + 1 <= vl) ? e1 : 0.f;
            e2 = (n0 <= vl) ? e2 : 0.f;
            e3 = (n0 + 1 <= vl) ? e3 : 0.f;
            ps0 += e0 + e1;
            ps1 += e2 + e3;
            sacc[nt][0] = e0; sacc[nt][1] = e1;
            sacc[nt][2] = e2; sacc[nt][3] = e3;
        }

        CP_WAIT(0);          // V ready
        __syncthreads();

        // ---- O += P @ V (P regs -> A-frags; V via ldmatrix.trans) ----
#pragma unroll
        for (int s = 0; s < 8; s++) {
            uint32_t ph0, pl0, ph1, pl1, ph2, pl2, ph3, pl3;
            split_pack(sacc[2 * s][0], sacc[2 * s][1], ph0, pl0);
            split_pack(sacc[2 * s][2], sacc[2 * s][3], ph1, pl1);
            split_pack(sacc[2 * s + 1][0], sacc[2 * s + 1][1], ph2, pl2);
            split_pack(sacc[2 * s + 1][2], sacc[2 * s + 1][3], ph3, pl3);
#pragma unroll
            for (int p = 0; p < 8; p++) {
                uint32_t vh[4], vo[4];
                LDSM4T(vh, vbb + 4352 * s + 32 * p);
                LDSM4T(vo, vbb + 4 * PT_U32 + 4352 * s + 32 * p);
                mma16816(oacc[2 * p], ph0, ph1, ph2, ph3, vh[0], vh[1]);
                mma16816(oacc[2 * p], ph0, ph1, ph2, ph3, vo[0], vo[1]);
                mma16816(oacc[2 * p], pl0, pl1, pl2, pl3, vh[0], vh[1]);
                mma16816(oacc[2 * p + 1], ph0, ph1, ph2, ph3, vh[2], vh[3]);
                mma16816(oacc[2 * p + 1], ph0, ph1, ph2, ph3, vo[2], vo[3]);
                mma16816(oacc[2 * p + 1], pl0, pl1, pl2, pl3, vh[2], vh[3]);
            }
        }

        if (c + 1 < nchunk) {   // prefetch next K/V chunk
            __syncthreads();    // all warps done with current K/V smem
            size_t nb = (size_t)(b * 4 + c + 1) * TILE_U32;
            cpa_tile(smb + 8 * PT_U32, g_kh + nb, tid);
            cpa_tile(smb + 12 * PT_U32, g_kl + nb, tid);
            CP_COMMIT();
            cpa_tile(smb + 16 * PT_U32, g_vvh + nb, tid);
            cpa_tile(smb + 20 * PT_U32, g_vvl + nb, tid);
            CP_COMMIT();
        }
    }

    // ---- row sums + epilogue with analytic mask fold ----
    ps0 += __shfl_xor_sync(0xffffffffu, ps0, 1);
    ps0 += __shfl_xor_sync(0xffffffffu, ps0, 2);
    ps1 += __shfl_xor_sync(0xffffffffu, ps1, 1);
    ps1 += __shfl_xor_sync(0xffffffffu, ps1, 2);
    float wm = __expf(MASKF);
    float nm = (float)(N_ - 1 - vl) * wm;
    float rt0 = 1.f / (ps0 + nm);
    float rt1 = 1.f / (ps1 + nm);
    const float* vs = g_vsuf + b * 128;
    size_t rg = (size_t)b * N_ + qt * 128 + r0 + g;
#pragma unroll
    for (int nt = 0; nt < 16; nt++) {
        int col = 8 * nt + 2 * t;
        float v0 = __ldg(vs + col), v1 = __ldg(vs + col + 1);
        float2 o0 = make_float2((oacc[nt][0] + wm * v0) * rt0,
                                (oacc[nt][1] + wm * v1) * rt0);
        float2 o1 = make_float2((oacc[nt][2] + wm * v0) * rt1,
                                (oacc[nt][3] + wm * v1) * rt1);
        *(float2*)(out + rg * 128 + col) = o0;
        *(float2*)(out + (rg + 8) * 128 + col) = o1;
    }
}

// ---- launch ----
extern "C" void kernel_launch(void* const* d_in, const int* in_sizes, int n_in,
                              void* d_out, int out_size) {
    const float* x  = (const float*)d_in[0];
    const float* Wq = (const float*)d_in[1];
    const float* bq = (const float*)d_in[2];
    const float* Wk = (const float*)d_in[3];
    const float* bk = (const float*)d_in[4];
    const float* Wv = (const float*)d_in[5];
    const float* bv = (const float*)d_in[6];
    const void*  vl = d_in[7];

    cudaFuncSetAttribute(qkv_kernel, cudaFuncAttributeMaxDynamicSharedMemorySize, QKV_SMEM);
    cudaFuncSetAttribute(attn_kernel, cudaFuncAttributeMaxDynamicSharedMemorySize, ATTN_SMEM);

    decode_vl_kernel<<<1, 256>>>(vl);
    prep_all_kernel<<<B_ * 4 + 3, 256>>>(x, Wq, Wk, Wv);
    xsum_kernel<<<dim3(B_, 4), 128>>>(x);
    vsuf_gemv_kernel<<<B_, 128>>>(Wv, bv);
    qkv_kernel<<<dim3(B_ * 4, 3), 256, QKV_SMEM>>>(bq, bk, bv);
    attn_kernel<<<dim3(B_, 4), 256, ATTN_SMEM>>>((float*)d_out);
}

// round 12
// speedup vs baseline: 2.9816x; 1.0860x over previous
#include <cuda_runtime.h>
#include <cuda_bf16.h>
#include <cstdint>

#define B_ 128
#define N_ 512
#define MASKF (-1e-6f)

#define TILE_U32 8192        // 128x128 bf16 tile = 128 rows x 64 u32 (unpadded)
#define PROW 68              // padded SMEM row stride (u32) = 272B
#define PT_U32 (128 * PROW)  // padded tile u32 count

// ---- global scratch (static: allocation-free) ----
__device__ __align__(16) uint32_t g_xh[(size_t)B_ * 4 * TILE_U32];
__device__ __align__(16) uint32_t g_xl[(size_t)B_ * 4 * TILE_U32];
__device__ __align__(16) uint32_t g_qh[(size_t)B_ * 4 * TILE_U32];
__device__ __align__(16) uint32_t g_ql[(size_t)B_ * 4 * TILE_U32];
__device__ __align__(16) uint32_t g_kh[(size_t)B_ * 4 * TILE_U32];
__device__ __align__(16) uint32_t g_kl[(size_t)B_ * 4 * TILE_U32];
__device__ __align__(16) uint32_t g_vvh[(size_t)B_ * 4 * TILE_U32];  // V K-major
__device__ __align__(16) uint32_t g_vvl[(size_t)B_ * 4 * TILE_U32];
__device__ __align__(16) uint32_t g_wth[3 * TILE_U32];  // W^T hi (q,k,v)
__device__ __align__(16) uint32_t g_wtl[3 * TILE_U32];
__device__ float g_xsum4[B_ * 4 * 128];  // per-tile masked-row column sums
__device__ float g_vsuf[B_ * 128];
__device__ int   g_vl[B_];

// ---- helpers ----
__device__ __forceinline__ uint32_t smem_u32(const void* p) {
    uint32_t a;
    asm("{ .reg .u64 t; cvta.to.shared.u64 t, %1; cvt.u32.u64 %0, t; }" : "=r"(a) : "l"(p));
    return a;
}
// fast two-term bf16 split of a float pair: h = [bf(f1)|bf(f0)], l = residuals
__device__ __forceinline__ void split_pack(float f0, float f1,
                                           uint32_t& h, uint32_t& l) {
    asm("cvt.rn.bf16x2.f32 %0, %1, %2;" : "=r"(h) : "f"(f1), "f"(f0));
    float hf0 = __uint_as_float(h << 16);
    float hf1 = __uint_as_float(h & 0xffff0000u);
    float l0 = f0 - hf0, l1 = f1 - hf1;
    asm("cvt.rn.bf16x2.f32 %0, %1, %2;" : "=r"(l) : "f"(l1), "f"(l0));
}
__device__ __forceinline__ void mma16816(float c[4], uint32_t a0, uint32_t a1,
                                         uint32_t a2, uint32_t a3,
                                         uint32_t b0, uint32_t b1) {
    asm volatile(
        "mma.sync.aligned.m16n8k16.row.col.f32.bf16.bf16.f32 "
        "{%0,%1,%2,%3}, {%4,%5,%6,%7}, {%8,%9}, {%0,%1,%2,%3};"
        : "+f"(c[0]), "+f"(c[1]), "+f"(c[2]), "+f"(c[3])
        : "r"(a0), "r"(a1), "r"(a2), "r"(a3), "r"(b0), "r"(b1));
}
__device__ __forceinline__ void mma3x(float c[4], const uint32_t ah[4],
                                      const uint32_t al[4],
                                      uint32_t bh0, uint32_t bh1,
                                      uint32_t bl0, uint32_t bl1) {
    mma16816(c, ah[0], ah[1], ah[2], ah[3], bh0, bh1);
    mma16816(c, ah[0], ah[1], ah[2], ah[3], bl0, bl1);
    mma16816(c, al[0], al[1], al[2], al[3], bh0, bh1);
}
#define LDSM4(R, a)                                                            \
    asm volatile("ldmatrix.sync.aligned.m8n8.x4.shared.b16 {%0,%1,%2,%3}, [%4];" \
        : "=r"((R)[0]), "=r"((R)[1]), "=r"((R)[2]), "=r"((R)[3]) : "r"(a))
#define LDSM4T(R, a)                                                           \
    asm volatile("ldmatrix.sync.aligned.m8n8.x4.trans.shared.b16 {%0,%1,%2,%3}, [%4];" \
        : "=r"((R)[0]), "=r"((R)[1]), "=r"((R)[2]), "=r"((R)[3]) : "r"(a))
#define CP16(saddr, gptr)                                                      \
    asm volatile("cp.async.cg.shared.global [%0], [%1], 16;" :: "r"(saddr), "l"(gptr))
#define CP_COMMIT() asm volatile("cp.async.commit_group;" ::: "memory")
#define CP_WAIT(n)  asm volatile("cp.async.wait_group %0;" :: "n"(n) : "memory")

// cp.async one unpadded 32KB tile -> padded smem (stride 17 float4/row-of-16)
__device__ __forceinline__ void cpa_tile(uint32_t dst_byte, const uint32_t* src, int tid) {
    const float4* s4 = (const float4*)src;
#pragma unroll
    for (int i = tid; i < 2048; i += 256)
        CP16(dst_byte + ((i >> 4) * 17 + (i & 15)) * 16, s4 + i);
}
// degree-6 exp2 polynomial exp (FFMA pipe); valid for |x| <~ 80
__device__ __forceinline__ float exp_poly(float x) {
    float y = x * 1.4426950408889634f;
    int ni = __float2int_rn(y);
    float f = y - __int2float_rn(ni);
    float p = 1.54035e-4f;
    p = fmaf(p, f, 1.33336e-3f);
    p = fmaf(p, f, 9.61813e-3f);
    p = fmaf(p, f, 5.55041e-2f);
    p = fmaf(p, f, 2.402265e-1f);
    p = fmaf(p, f, 6.931472e-1f);
    p = fmaf(p, f, 1.0f);
    return __int_as_float(__float_as_int(p) + (ni << 23));
}

// ---- decode valid_len (runtime int64-vs-int32 detect) ----
__global__ __launch_bounds__(128)
void decode_vl_kernel(const void* __restrict__ raw) {
    __shared__ int bad;
    int t = threadIdx.x;
    if (t == 0) bad = 0;
    __syncthreads();
    if (t < 64) {
        long long v = ((const long long*)raw)[t];
        if (v < 0 || v >= N_) atomicOr(&bad, 1);
    }
    __syncthreads();
    if (t < B_) g_vl[t] = bad ? ((const int*)raw)[t] : (int)((const long long*)raw)[t];
}

// ---- merged prep: blocks 0-2 W^T tiles; blocks 3.. x-split + fused xsum ----
__global__ __launch_bounds__(256)
void prep_all_kernel(const float* __restrict__ x, const float* __restrict__ Wq,
                     const float* __restrict__ Wk, const float* __restrict__ Wv) {
    __shared__ float sxs[128];
    int blk = blockIdx.x, tid = threadIdx.x;
    if (blk < 3) {
        const float* W = (blk == 0) ? Wq : (blk == 1) ? Wk : Wv;
        int w = tid & 127;
        int c0 = (tid >> 7) * 64;  // two half-ranges of c per w
        size_t base = (size_t)blk * TILE_U32;
        for (int c = c0; c < c0 + 64; c += 2) {
            uint32_t h, l;
            split_pack(W[c * 128 + w], W[(c + 1) * 128 + w], h, l);
            g_wth[base + w * 64 + (c >> 1)] = h;
            g_wtl[base + w * 64 + (c >> 1)] = l;
        }
    } else {
        int xb = blk - 3;
        int b = xb >> 2, tile = xb & 3;
        int vl = g_vl[b];
        int lo = vl + 1 - tile * 128;       // first masked local row
        if (lo < 0) lo = 0;
        bool anymask = (lo < 128);
        if (tid < 128) sxs[tid] = 0.f;
        __syncthreads();
        const float4* xg = (const float4*)(x + (size_t)xb * 128 * 128);
        uint2* dh = (uint2*)(g_xh + (size_t)xb * TILE_U32);
        uint2* dl = (uint2*)(g_xl + (size_t)xb * TILE_U32);
#pragma unroll
        for (int i = tid; i < 4096; i += 256) {
            float4 v = xg[i];
            uint32_t h0, l0, h1, l1;
            split_pack(v.x, v.y, h0, l0);
            split_pack(v.z, v.w, h1, l1);
            dh[i] = make_uint2(h0, h1);
            dl[i] = make_uint2(l0, l1);
            if (anymask && (i >> 5) >= lo) {   // masked row: fold into column sums
                int c4 = (i & 31) << 2;
                atomicAdd(&sxs[c4], v.x);
                atomicAdd(&sxs[c4 + 1], v.y);
                atomicAdd(&sxs[c4 + 2], v.z);
                atomicAdd(&sxs[c4 + 3], v.w);
            }
        }
        __syncthreads();
        if (tid < 128) g_xsum4[xb * 128 + tid] = sxs[tid];
    }
}

// ---- vsuf[b][w] = (sum of 4 tile slots)@Wv + cnt*bv; 2-way c-split ----
__global__ __launch_bounds__(256)
void vsuf_gemv_kernel(const float* __restrict__ Wv, const float* __restrict__ bv) {
    __shared__ float xs[128];
    __shared__ float pacc[2][128];
    int b = blockIdx.x, tid = threadIdx.x;
    int vl = g_vl[b];
    if (tid < 128) {
        int base = b * 4 * 128 + tid;
        xs[tid] = g_xsum4[base] + g_xsum4[base + 128] +
                  g_xsum4[base + 256] + g_xsum4[base + 384];
    }
    __syncthreads();
    int w = tid & 127, half = tid >> 7;
    float acc = 0.f;
    int c0 = half * 64;
#pragma unroll 16
    for (int c = c0; c < c0 + 64; c++)
        acc = fmaf(xs[c], __ldg(Wv + c * 128 + w), acc);
    pacc[half][w] = acc;
    __syncthreads();
    if (tid < 128)
        g_vsuf[b * 128 + tid] = pacc[0][tid] + pacc[1][tid] +
                                (float)(N_ - 1 - vl) * __ldg(bv + tid);
}

// ===========================================================================
// QKV: grid (512, 3). One block per (token-tile, matrix). 3-term bf16 GEMM.
// K/V tiles skipped when fully masked. V stored K-major (no transpose).
// ===========================================================================
#define QKV_SMEM (16 * PT_U32)
__global__ __launch_bounds__(256)
void qkv_kernel(const float* __restrict__ bq, const float* __restrict__ bk,
                const float* __restrict__ bv) {
    extern __shared__ uint32_t smu[];
    int tid = threadIdx.x, warp = tid >> 5, lane = tid & 31;
    int g = lane >> 2, t = lane & 3, r0 = warp * 16;
    int blk = blockIdx.x, mat = blockIdx.y;
    int b = blk >> 2, tile = blk & 3, vl = g_vl[b];
    if (mat && tile * 128 > vl) return;

    uint32_t smb = smem_u32(smu);
    cpa_tile(smb, g_xh + (size_t)blk * TILE_U32, tid);
    cpa_tile(smb + 4 * PT_U32, g_xl + (size_t)blk * TILE_U32, tid);
    cpa_tile(smb + 8 * PT_U32, g_wth + (size_t)mat * TILE_U32, tid);
    cpa_tile(smb + 12 * PT_U32, g_wtl + (size_t)mat * TILE_U32, tid);
    CP_COMMIT();
    CP_WAIT(0);
    __syncthreads();

    float sacc[16][4];
#pragma unroll
    for (int nt = 0; nt < 16; nt++)
#pragma unroll
        for (int i = 0; i < 4; i++) sacc[nt][i] = 0.f;

    uint32_t a_base = smb + 4 * ((r0 + (lane & 15)) * PROW + ((lane & 16) >> 2));
    uint32_t b_base = smb + 8 * PT_U32 +
                      4 * (((lane & 7) + ((lane & 16) >> 1)) * PROW + ((lane & 8) >> 1));
#pragma unroll 1
    for (int s = 0; s < 8; s++) {
        uint32_t ah[4], al[4];
        LDSM4(ah, a_base + 32 * s);
        LDSM4(al, a_base + 4 * PT_U32 + 32 * s);
#pragma unroll
        for (int p = 0; p < 8; p++) {
            uint32_t bh[4], bl[4];
            LDSM4(bh, b_base + 4352 * p + 32 * s);
            LDSM4(bl, b_base + 4 * PT_U32 + 4352 * p + 32 * s);
            mma3x(sacc[2 * p], ah, al, bh[0], bh[1], bl[0], bl[1]);
            mma3x(sacc[2 * p + 1], ah, al, bh[2], bh[3], bl[2], bl[3]);
        }
    }

    const float* bias = (mat == 0) ? bq : (mat == 1) ? bk : bv;
    uint32_t* dh = (mat == 0) ? g_qh : (mat == 1) ? g_kh : g_vvh;
    uint32_t* dl = (mat == 0) ? g_ql : (mat == 1) ? g_kl : g_vvl;
    size_t rg = (size_t)blk * 128 + r0 + g;
#pragma unroll
    for (int nt = 0; nt < 16; nt++) {
        int col = 8 * nt + 2 * t;
        float b0 = __ldg(bias + col), b1 = __ldg(bias + col + 1);
        uint32_t h, l;
        split_pack(sacc[nt][0] + b0, sacc[nt][1] + b1, h, l);
        dh[rg * 64 + 4 * nt + t] = h;
        dl[rg * 64 + 4 * nt + t] = l;
        split_pack(sacc[nt][2] + b0, sacc[nt][3] + b1, h, l);
        dh[(rg + 8) * 64 + 4 * nt + t] = h;
        dl[(rg + 8) * 64 + 4 * nt + t] = l;
    }
}

// ===========================================================================
// Attention: grid (4, 128) — qt fastest so same-batch blocks share K/V in L2.
// ldmatrix fragments, hybrid exp, cp.async prefetch.
// ===========================================================================
#define ATTN_SMEM (24 * PT_U32)
__global__ __launch_bounds__(256)
void attn_kernel(float* __restrict__ out) {
    extern __shared__ uint32_t smu[];
    int tid = threadIdx.x, warp = tid >> 5, lane = tid & 31;
    int g = lane >> 2, t = lane & 3, r0 = warp * 16;
    int qt = blockIdx.x, b = blockIdx.y;
    int vl = g_vl[b], nchunk = (vl >> 7) + 1;
    uint32_t smb = smem_u32(smu);

    size_t qb = (size_t)(b * 4 + qt) * TILE_U32;
    cpa_tile(smb, g_qh + qb, tid);
    cpa_tile(smb + 4 * PT_U32, g_ql + qb, tid);
    CP_COMMIT();
    size_t kb0 = (size_t)(b * 4) * TILE_U32;
    cpa_tile(smb + 8 * PT_U32, g_kh + kb0, tid);
    cpa_tile(smb + 12 * PT_U32, g_kl + kb0, tid);
    CP_COMMIT();
    cpa_tile(smb + 16 * PT_U32, g_vvh + kb0, tid);
    cpa_tile(smb + 20 * PT_U32, g_vvl + kb0, tid);
    CP_COMMIT();

    uint32_t qa = smb + 4 * ((r0 + (lane & 15)) * PROW + ((lane & 16) >> 2));
    uint32_t kbb = smb + 8 * PT_U32 +
                   4 * (((lane & 7) + ((lane & 16) >> 1)) * PROW + ((lane & 8) >> 1));
    uint32_t vbb = smb + 16 * PT_U32 +
                   4 * (((lane & 7) + (lane & 8)) * PROW + ((lane & 16) >> 2));

    float oacc[16][4];
#pragma unroll
    for (int nt = 0; nt < 16; nt++)
#pragma unroll
        for (int i = 0; i < 4; i++) oacc[nt][i] = 0.f;
    float ps0 = 0.f, ps1 = 0.f;

#pragma unroll 1
    for (int c = 0; c < nchunk; c++) {
        CP_WAIT(1);          // Q+K ready (V may still be in flight)
        __syncthreads();

        // ---- S = Q @ K^T ----
        float sacc[16][4];
#pragma unroll
        for (int nt = 0; nt < 16; nt++)
#pragma unroll
            for (int i = 0; i < 4; i++) sacc[nt][i] = 0.f;
#pragma unroll 1
        for (int s = 0; s < 8; s++) {
            uint32_t ah[4], al[4];
            LDSM4(ah, qa + 32 * s);
            LDSM4(al, qa + 4 * PT_U32 + 32 * s);
#pragma unroll
            for (int p = 0; p < 8; p++) {
                uint32_t bh[4], bl[4];
                LDSM4(bh, kbb + 4352 * p + 32 * s);
                LDSM4(bl, kbb + 4 * PT_U32 + 4352 * p + 32 * s);
                mma3x(sacc[2 * p], ah, al, bh[0], bh[1], bl[0], bl[1]);
                mma3x(sacc[2 * p + 1], ah, al, bh[2], bh[3], bl[2], bl[3]);
            }
        }

        // ---- masked exp (no max subtraction), hybrid MUFU/FFMA ----
        int cn = c * 128 + 2 * t;
#pragma unroll
        for (int nt = 0; nt < 16; nt++) {
            int n0 = cn + 8 * nt;
            float e0, e1, e2, e3;
            if (nt & 1) {
                e0 = exp_poly(sacc[nt][0]); e1 = exp_poly(sacc[nt][1]);
                e2 = exp_poly(sacc[nt][2]); e3 = exp_poly(sacc[nt][3]);
            } else {
                e0 = __expf(sacc[nt][0]); e1 = __expf(sacc[nt][1]);
                e2 = __expf(sacc[nt][2]); e3 = __expf(sacc[nt][3]);
            }
            e0 = (n0 <= vl) ? e0 : 0.f;
            e1 = (n0 + 1 <= vl) ? e1 : 0.f;
            e2 = (n0 <= vl) ? e2 : 0.f;
            e3 = (n0 + 1 <= vl) ? e3 : 0.f;
            ps0 += e0 + e1;
            ps1 += e2 + e3;
            sacc[nt][0] = e0; sacc[nt][1] = e1;
            sacc[nt][2] = e2; sacc[nt][3] = e3;
        }

        CP_WAIT(0);          // V ready
        __syncthreads();

        // ---- O += P @ V (P regs -> A-frags; V via ldmatrix.trans) ----
#pragma unroll
        for (int s = 0; s < 8; s++) {
            uint32_t ph0, pl0, ph1, pl1, ph2, pl2, ph3, pl3;
            split_pack(sacc[2 * s][0], sacc[2 * s][1], ph0, pl0);
            split_pack(sacc[2 * s][2], sacc[2 * s][3], ph1, pl1);
            split_pack(sacc[2 * s + 1][0], sacc[2 * s + 1][1], ph2, pl2);
            split_pack(sacc[2 * s + 1][2], sacc[2 * s + 1][3], ph3, pl3);
#pragma unroll
            for (int p = 0; p < 8; p++) {
                uint32_t vh[4], vo[4];
                LDSM4T(vh, vbb + 4352 * s + 32 * p);
                LDSM4T(vo, vbb + 4 * PT_U32 + 4352 * s + 32 * p);
                mma16816(oacc[2 * p], ph0, ph1, ph2, ph3, vh[0], vh[1]);
                mma16816(oacc[2 * p], ph0, ph1, ph2, ph3, vo[0], vo[1]);
                mma16816(oacc[2 * p], pl0, pl1, pl2, pl3, vh[0], vh[1]);
                mma16816(oacc[2 * p + 1], ph0, ph1, ph2, ph3, vh[2], vh[3]);
                mma16816(oacc[2 * p + 1], ph0, ph1, ph2, ph3, vo[2], vo[3]);
                mma16816(oacc[2 * p + 1], pl0, pl1, pl2, pl3, vh[2], vh[3]);
            }
        }

        if (c + 1 < nchunk) {   // prefetch next K/V chunk
            __syncthreads();    // all warps done with current K/V smem
            size_t nb = (size_t)(b * 4 + c + 1) * TILE_U32;
            cpa_tile(smb + 8 * PT_U32, g_kh + nb, tid);
            cpa_tile(smb + 12 * PT_U32, g_kl + nb, tid);
            CP_COMMIT();
            cpa_tile(smb + 16 * PT_U32, g_vvh + nb, tid);
            cpa_tile(smb + 20 * PT_U32, g_vvl + nb, tid);
            CP_COMMIT();
        }
    }

    // ---- row sums + epilogue with analytic mask fold ----
    ps0 += __shfl_xor_sync(0xffffffffu, ps0, 1);
    ps0 += __shfl_xor_sync(0xffffffffu, ps0, 2);
    ps1 += __shfl_xor_sync(0xffffffffu, ps1, 1);
    ps1 += __shfl_xor_sync(0xffffffffu, ps1, 2);
    float wm = __expf(MASKF);
    float nm = (float)(N_ - 1 - vl) * wm;
    float rt0 = 1.f / (ps0 + nm);
    float rt1 = 1.f / (ps1 + nm);
    const float* vs = g_vsuf + b * 128;
    size_t rg = (size_t)b * N_ + qt * 128 + r0 + g;
#pragma unroll
    for (int nt = 0; nt < 16; nt++) {
        int col = 8 * nt + 2 * t;
        float v0 = __ldg(vs + col), v1 = __ldg(vs + col + 1);
        float2 o0 = make_float2((oacc[nt][0] + wm * v0) * rt0,
                                (oacc[nt][1] + wm * v1) * rt0);
        float2 o1 = make_float2((oacc[nt][2] + wm * v0) * rt1,
                                (oacc[nt][3] + wm * v1) * rt1);
        *(float2*)(out + rg * 128 + col) = o0;
        *(float2*)(out + (rg + 8) * 128 + col) = o1;
    }
}

// ---- launch ----
extern "C" void kernel_launch(void* const* d_in, const int* in_sizes, int n_in,
                              void* d_out, int out_size) {
    const float* x  = (const float*)d_in[0];
    const float* Wq = (const float*)d_in[1];
    const float* bq = (const float*)d_in[2];
    const float* Wk = (const float*)d_in[3];
    const float* bk = (const float*)d_in[4];
    const float* Wv = (const float*)d_in[5];
    const float* bv = (const float*)d_in[6];
    const void*  vl = d_in[7];

    cudaFuncSetAttribute(qkv_kernel, cudaFuncAttributeMaxDynamicSharedMemorySize, QKV_SMEM);
    cudaFuncSetAttribute(attn_kernel, cudaFuncAttributeMaxDynamicSharedMemorySize, ATTN_SMEM);

    decode_vl_kernel<<<1, 128>>>(vl);
    prep_all_kernel<<<B_ * 4 + 3, 256>>>(x, Wq, Wk, Wv);
    vsuf_gemv_kernel<<<B_, 256>>>(Wv, bv);
    qkv_kernel<<<dim3(B_ * 4, 3), 256, QKV_SMEM>>>(bq, bk, bv);
    attn_kernel<<<dim3(4, B_), 256, ATTN_SMEM>>>((float*)d_out);
}

// round 15
// speedup vs baseline: 2.9978x; 1.0055x over previous
#include <cuda_runtime.h>
#include <cuda_bf16.h>
#include <cstdint>

#define B_ 128
#define N_ 512
#define MASKF (-1e-6f)

#define TILE_U32 8192        // 128x128 bf16 tile = 128 rows x 64 u32 (unpadded)
#define PROW 68              // padded SMEM row stride (u32) = 272B
#define PT_U32 (128 * PROW)  // padded tile u32 count

// ---- global scratch (static: allocation-free) ----
__device__ __align__(16) uint32_t g_xh[(size_t)B_ * 4 * TILE_U32];
__device__ __align__(16) uint32_t g_xl[(size_t)B_ * 4 * TILE_U32];
__device__ __align__(16) uint32_t g_qh[(size_t)B_ * 4 * TILE_U32];
__device__ __align__(16) uint32_t g_ql[(size_t)B_ * 4 * TILE_U32];
__device__ __align__(16) uint32_t g_kh[(size_t)B_ * 4 * TILE_U32];
__device__ __align__(16) uint32_t g_kl[(size_t)B_ * 4 * TILE_U32];
__device__ __align__(16) uint32_t g_vvh[(size_t)B_ * 4 * TILE_U32];  // V K-major
__device__ __align__(16) uint32_t g_vvl[(size_t)B_ * 4 * TILE_U32];
__device__ __align__(16) uint32_t g_wth[3 * TILE_U32];  // W^T hi (q,k,v)
__device__ __align__(16) uint32_t g_wtl[3 * TILE_U32];
__device__ float g_xsum4[B_ * 4 * 128];  // per-tile masked-row column sums
__device__ float g_vsuf[B_ * 128];
__device__ int   g_vl[B_];

// ---- helpers ----
__device__ __forceinline__ uint32_t smem_u32(const void* p) {
    uint32_t a;
    asm("{ .reg .u64 t; cvta.to.shared.u64 t, %1; cvt.u32.u64 %0, t; }" : "=r"(a) : "l"(p));
    return a;
}
// fast two-term bf16 split of a float pair: h = [bf(f1)|bf(f0)], l = residuals
__device__ __forceinline__ void split_pack(float f0, float f1,
                                           uint32_t& h, uint32_t& l) {
    asm("cvt.rn.bf16x2.f32 %0, %1, %2;" : "=r"(h) : "f"(f1), "f"(f0));
    float hf0 = __uint_as_float(h << 16);
    float hf1 = __uint_as_float(h & 0xffff0000u);
    float l0 = f0 - hf0, l1 = f1 - hf1;
    asm("cvt.rn.bf16x2.f32 %0, %1, %2;" : "=r"(l) : "f"(l1), "f"(l0));
}
__device__ __forceinline__ void mma16816(float c[4], uint32_t a0, uint32_t a1,
                                         uint32_t a2, uint32_t a3,
                                         uint32_t b0, uint32_t b1) {
    asm volatile(
        "mma.sync.aligned.m16n8k16.row.col.f32.bf16.bf16.f32 "
        "{%0,%1,%2,%3}, {%4,%5,%6,%7}, {%8,%9}, {%0,%1,%2,%3};"
        : "+f"(c[0]), "+f"(c[1]), "+f"(c[2]), "+f"(c[3])
        : "r"(a0), "r"(a1), "r"(a2), "r"(a3), "r"(b0), "r"(b1));
}
__device__ __forceinline__ void mma3x(float c[4], const uint32_t ah[4],
                                      const uint32_t al[4],
                                      uint32_t bh0, uint32_t bh1,
                                      uint32_t bl0, uint32_t bl1) {
    mma16816(c, ah[0], ah[1], ah[2], ah[3], bh0, bh1);
    mma16816(c, ah[0], ah[1], ah[2], ah[3], bl0, bl1);
    mma16816(c, al[0], al[1], al[2], al[3], bh0, bh1);
}
#define LDSM4(R, a)                                                            \
    asm volatile("ldmatrix.sync.aligned.m8n8.x4.shared.b16 {%0,%1,%2,%3}, [%4];" \
        : "=r"((R)[0]), "=r"((R)[1]), "=r"((R)[2]), "=r"((R)[3]) : "r"(a))
#define LDSM4T(R, a)                                                           \
    asm volatile("ldmatrix.sync.aligned.m8n8.x4.trans.shared.b16 {%0,%1,%2,%3}, [%4];" \
        : "=r"((R)[0]), "=r"((R)[1]), "=r"((R)[2]), "=r"((R)[3]) : "r"(a))
#define CP16(saddr, gptr)                                                      \
    asm volatile("cp.async.cg.shared.global [%0], [%1], 16;" :: "r"(saddr), "l"(gptr))
#define CP_COMMIT() asm volatile("cp.async.commit_group;" ::: "memory")
#define CP_WAIT(n)  asm volatile("cp.async.wait_group %0;" :: "n"(n) : "memory")

// cp.async one unpadded 32KB tile -> padded smem (stride 17 float4/row-of-16)
template <int NT>
__device__ __forceinline__ void cpa_tile(uint32_t dst_byte, const uint32_t* src, int tid) {
    const float4* s4 = (const float4*)src;
#pragma unroll
    for (int i = tid; i < 2048; i += NT)
        CP16(dst_byte + ((i >> 4) * 17 + (i & 15)) * 16, s4 + i);
}
// degree-6 exp2 polynomial exp (FFMA pipe); valid for |x| <~ 80
__device__ __forceinline__ float exp_poly(float x) {
    float y = x * 1.4426950408889634f;
    int ni = __float2int_rn(y);
    float f = y - __int2float_rn(ni);
    float p = 1.54035e-4f;
    p = fmaf(p, f, 1.33336e-3f);
    p = fmaf(p, f, 9.61813e-3f);
    p = fmaf(p, f, 5.55041e-2f);
    p = fmaf(p, f, 2.402265e-1f);
    p = fmaf(p, f, 6.931472e-1f);
    p = fmaf(p, f, 1.0f);
    return __int_as_float(__float_as_int(p) + (ni << 23));
}

// ---- decode valid_len (runtime int64-vs-int32 detect) ----
__global__ __launch_bounds__(128)
void decode_vl_kernel(const void* __restrict__ raw) {
    __shared__ int bad;
    int t = threadIdx.x;
    if (t == 0) bad = 0;
    __syncthreads();
    if (t < 64) {
        long long v = ((const long long*)raw)[t];
        if (v < 0 || v >= N_) atomicOr(&bad, 1);
    }
    __syncthreads();
    if (t < B_) g_vl[t] = bad ? ((const int*)raw)[t] : (int)((const long long*)raw)[t];
}

// ---- merged prep: blocks 0-2 W^T tiles; blocks 3.. x-split + fused xsum ----
__global__ __launch_bounds__(256)
void prep_all_kernel(const float* __restrict__ x, const float* __restrict__ Wq,
                     const float* __restrict__ Wk, const float* __restrict__ Wv) {
    __shared__ float sxs[128];
    int blk = blockIdx.x, tid = threadIdx.x;
    if (blk < 3) {
        const float* W = (blk == 0) ? Wq : (blk == 1) ? Wk : Wv;
        int w = tid & 127;
        int c0 = (tid >> 7) * 64;  // two half-ranges of c per w
        size_t base = (size_t)blk * TILE_U32;
        for (int c = c0; c < c0 + 64; c += 2) {
            uint32_t h, l;
            split_pack(W[c * 128 + w], W[(c + 1) * 128 + w], h, l);
            g_wth[base + w * 64 + (c >> 1)] = h;
            g_wtl[base + w * 64 + (c >> 1)] = l;
        }
    } else {
        int xb = blk - 3;
        int b = xb >> 2, tile = xb & 3;
        int vl = g_vl[b];
        int lo = vl + 1 - tile * 128;       // first masked local row
        if (lo < 0) lo = 0;
        bool anymask = (lo < 128);
        if (tid < 128) sxs[tid] = 0.f;
        __syncthreads();
        const float4* xg = (const float4*)(x + (size_t)xb * 128 * 128);
        uint2* dh = (uint2*)(g_xh + (size_t)xb * TILE_U32);
        uint2* dl = (uint2*)(g_xl + (size_t)xb * TILE_U32);
#pragma unroll
        for (int i = tid; i < 4096; i += 256) {
            float4 v = xg[i];
            uint32_t h0, l0, h1, l1;
            split_pack(v.x, v.y, h0, l0);
            split_pack(v.z, v.w, h1, l1);
            dh[i] = make_uint2(h0, h1);
            dl[i] = make_uint2(l0, l1);
            if (anymask && (i >> 5) >= lo) {   // masked row: fold into column sums
                int c4 = (i & 31) << 2;
                atomicAdd(&sxs[c4], v.x);
                atomicAdd(&sxs[c4 + 1], v.y);
                atomicAdd(&sxs[c4 + 2], v.z);
                atomicAdd(&sxs[c4 + 3], v.w);
            }
        }
        __syncthreads();
        if (tid < 128) g_xsum4[xb * 128 + tid] = sxs[tid];
    }
}

// ---- vsuf[b][w] = (sum of 4 tile slots)@Wv + cnt*bv; 2-way c-split ----
__global__ __launch_bounds__(256)
void vsuf_gemv_kernel(const float* __restrict__ Wv, const float* __restrict__ bv) {
    __shared__ float xs[128];
    __shared__ float pacc[2][128];
    int b = blockIdx.x, tid = threadIdx.x;
    int vl = g_vl[b];
    if (tid < 128) {
        int base = b * 4 * 128 + tid;
        xs[tid] = g_xsum4[base] + g_xsum4[base + 128] +
                  g_xsum4[base + 256] + g_xsum4[base + 384];
    }
    __syncthreads();
    int w = tid & 127, half = tid >> 7;
    float acc = 0.f;
    int c0 = half * 64;
#pragma unroll 16
    for (int c = c0; c < c0 + 64; c++)
        acc = fmaf(xs[c], __ldg(Wv + c * 128 + w), acc);
    pacc[half][w] = acc;
    __syncthreads();
    if (tid < 128)
        g_vsuf[b * 128 + tid] = pacc[0][tid] + pacc[1][tid] +
                                (float)(N_ - 1 - vl) * __ldg(bv + tid);
}

// ===========================================================================
// QKV: grid (512, 3), 512 threads (16 warps). Warp (wr,wc) computes a 16x64
// output tile: wr = rows, wc = 64-col half. 3-term bf16 GEMM, unroll-2 k-loop.
// K/V tiles skipped when fully masked. V stored K-major (no transpose).
// ===========================================================================
#define QKV_SMEM (16 * PT_U32)
__global__ __launch_bounds__(512)
void qkv_kernel(const float* __restrict__ bq, const float* __restrict__ bk,
                const float* __restrict__ bv) {
    extern __shared__ uint32_t smu[];
    int tid = threadIdx.x, warp = tid >> 5, lane = tid & 31;
    int g = lane >> 2, t = lane & 3;
    int wr = warp & 7, wc = warp >> 3;
    int r0 = wr * 16;
    int blk = blockIdx.x, mat = blockIdx.y;
    int b = blk >> 2, tile = blk & 3, vl = g_vl[b];
    if (mat && tile * 128 > vl) return;

    uint32_t smb = smem_u32(smu);
    cpa_tile<512>(smb, g_xh + (size_t)blk * TILE_U32, tid);
    cpa_tile<512>(smb + 4 * PT_U32, g_xl + (size_t)blk * TILE_U32, tid);
    cpa_tile<512>(smb + 8 * PT_U32, g_wth + (size_t)mat * TILE_U32, tid);
    cpa_tile<512>(smb + 12 * PT_U32, g_wtl + (size_t)mat * TILE_U32, tid);
    CP_COMMIT();
    CP_WAIT(0);
    __syncthreads();

    float sacc[8][4];
#pragma unroll
    for (int nt = 0; nt < 8; nt++)
#pragma unroll
        for (int i = 0; i < 4; i++) sacc[nt][i] = 0.f;

    uint32_t a_base = smb + 4 * ((r0 + (lane & 15)) * PROW + ((lane & 16) >> 2));
    uint32_t b_base = smb + 8 * PT_U32 + wc * 17408 +
                      4 * (((lane & 7) + ((lane & 16) >> 1)) * PROW + ((lane & 8) >> 1));
#pragma unroll 2
    for (int s = 0; s < 8; s++) {
        uint32_t ah[4], al[4];
        LDSM4(ah, a_base + 32 * s);
        LDSM4(al, a_base + 4 * PT_U32 + 32 * s);
#pragma unroll
        for (int p = 0; p < 4; p++) {
            uint32_t bh[4], bl[4];
            LDSM4(bh, b_base + 4352 * p + 32 * s);
            LDSM4(bl, b_base + 4 * PT_U32 + 4352 * p + 32 * s);
            mma3x(sacc[2 * p], ah, al, bh[0], bh[1], bl[0], bl[1]);
            mma3x(sacc[2 * p + 1], ah, al, bh[2], bh[3], bl[2], bl[3]);
        }
    }

    const float* bias = (mat == 0) ? bq : (mat == 1) ? bk : bv;
    uint32_t* dh = (mat == 0) ? g_qh : (mat == 1) ? g_kh : g_vvh;
    uint32_t* dl = (mat == 0) ? g_ql : (mat == 1) ? g_kl : g_vvl;
    size_t rg = (size_t)blk * 128 + r0 + g;
#pragma unroll
    for (int nt = 0; nt < 8; nt++) {
        int col = wc * 64 + 8 * nt + 2 * t;
        float b0 = __ldg(bias + col), b1 = __ldg(bias + col + 1);
        uint32_t h, l;
        split_pack(sacc[nt][0] + b0, sacc[nt][1] + b1, h, l);
        dh[rg * 64 + (col >> 1)] = h;
        dl[rg * 64 + (col >> 1)] = l;
        split_pack(sacc[nt][2] + b0, sacc[nt][3] + b1, h, l);
        dh[(rg + 8) * 64 + (col >> 1)] = h;
        dl[(rg + 8) * 64 + (col >> 1)] = l;
    }
}

// ===========================================================================
// Attention: grid (4, 128) — qt fastest so same-batch blocks share K/V in L2.
// ldmatrix fragments, hybrid exp, cp.async prefetch, unroll-2 S k-loop.
// ===========================================================================
#define ATTN_SMEM (24 * PT_U32)
__global__ __launch_bounds__(256)
void attn_kernel(float* __restrict__ out) {
    extern __shared__ uint32_t smu[];
    int tid = threadIdx.x, warp = tid >> 5, lane = tid & 31;
    int g = lane >> 2, t = lane & 3, r0 = warp * 16;
    int qt = blockIdx.x, b = blockIdx.y;
    int vl = g_vl[b], nchunk = (vl >> 7) + 1;
    uint32_t smb = smem_u32(smu);

    size_t qb = (size_t)(b * 4 + qt) * TILE_U32;
    cpa_tile<256>(smb, g_qh + qb, tid);
    cpa_tile<256>(smb + 4 * PT_U32, g_ql + qb, tid);
    CP_COMMIT();
    size_t kb0 = (size_t)(b * 4) * TILE_U32;
    cpa_tile<256>(smb + 8 * PT_U32, g_kh + kb0, tid);
    cpa_tile<256>(smb + 12 * PT_U32, g_kl + kb0, tid);
    CP_COMMIT();
    cpa_tile<256>(smb + 16 * PT_U32, g_vvh + kb0, tid);
    cpa_tile<256>(smb + 20 * PT_U32, g_vvl + kb0, tid);
    CP_COMMIT();

    uint32_t qa = smb + 4 * ((r0 + (lane & 15)) * PROW + ((lane & 16) >> 2));
    uint32_t kbb = smb + 8 * PT_U32 +
                   4 * (((lane & 7) + ((lane & 16) >> 1)) * PROW + ((lane & 8) >> 1));
    uint32_t vbb = smb + 16 * PT_U32 +
                   4 * (((lane & 7) + (lane & 8)) * PROW + ((lane & 16) >> 2));

    float oacc[16][4];
#pragma unroll
    for (int nt = 0; nt < 16; nt++)
#pragma unroll
        for (int i = 0; i < 4; i++) oacc[nt][i] = 0.f;
    float ps0 = 0.f, ps1 = 0.f;

#pragma unroll 1
    for (int c = 0; c < nchunk; c++) {
        CP_WAIT(1);          // Q+K ready (V may still be in flight)
        __syncthreads();

        // ---- S = Q @ K^T ----
        float sacc[16][4];
#pragma unroll
        for (int nt = 0; nt < 16; nt++)
#pragma unroll
            for (int i = 0; i < 4; i++) sacc[nt][i] = 0.f;
#pragma unroll 2
        for (int s = 0; s < 8; s++) {
            uint32_t ah[4], al[4];
            LDSM4(ah, qa + 32 * s);
            LDSM4(al, qa + 4 * PT_U32 + 32 * s);
#pragma unroll
            for (int p = 0; p < 8; p++) {
                uint32_t bh[4], bl[4];
                LDSM4(bh, kbb + 4352 * p + 32 * s);
                LDSM4(bl, kbb + 4 * PT_U32 + 4352 * p + 32 * s);
                mma3x(sacc[2 * p], ah, al, bh[0], bh[1], bl[0], bl[1]);
                mma3x(sacc[2 * p + 1], ah, al, bh[2], bh[3], bl[2], bl[3]);
            }
        }

        // ---- masked exp (no max subtraction), hybrid MUFU/FFMA ----
        int cn = c * 128 + 2 * t;
#pragma unroll
        for (int nt = 0; nt < 16; nt++) {
            int n0 = cn + 8 * nt;
            float e0, e1, e2, e3;
            if (nt & 1) {
                e0 = exp_poly(sacc[nt][0]); e1 = exp_poly(sacc[nt][1]);
                e2 = exp_poly(sacc[nt][2]); e3 = exp_poly(sacc[nt][3]);
            } else {
                e0 = __expf(sacc[nt][0]); e1 = __expf(sacc[nt][1]);
                e2 = __expf(sacc[nt][2]); e3 = __expf(sacc[nt][3]);
            }
            e0 = (n0 <= vl) ? e0 : 0.f;
            e1 = (n0 + 1 <= vl) ? e1 : 0.f;
            e2 = (n0 <= vl) ? e2 : 0.f;
            e3 = (n0 + 1 <= vl) ? e3 : 0.f;
            ps0 += e0 + e1;
            ps1 += e2 + e3;
            sacc[nt][0] = e0; sacc[nt][1] = e1;
            sacc[nt][2] = e2; sacc[nt][3] = e3;
        }

        CP_WAIT(0);          // V ready
        __syncthreads();

        // ---- O += P @ V (P regs -> A-frags; V via ldmatrix.trans) ----
#pragma unroll
        for (int s = 0; s < 8; s++) {
            uint32_t ph0, pl0, ph1, pl1, ph2, pl2, ph3, pl3;
            split_pack(sacc[2 * s][0], sacc[2 * s][1], ph0, pl0);
            split_pack(sacc[2 * s][2], sacc[2 * s][3], ph1, pl1);
            split_pack(sacc[2 * s + 1][0], sacc[2 * s + 1][1], ph2, pl2);
            split_pack(sacc[2 * s + 1][2], sacc[2 * s + 1][3], ph3, pl3);
#pragma unroll
            for (int p = 0; p < 8; p++) {
                uint32_t vh[4], vo[4];
                LDSM4T(vh, vbb + 4352 * s + 32 * p);
                LDSM4T(vo, vbb + 4 * PT_U32 + 4352 * s + 32 * p);
                mma16816(oacc[2 * p], ph0, ph1, ph2, ph3, vh[0], vh[1]);
                mma16816(oacc[2 * p], ph0, ph1, ph2, ph3, vo[0], vo[1]);
                mma16816(oacc[2 * p], pl0, pl1, pl2, pl3, vh[0], vh[1]);
                mma16816(oacc[2 * p + 1], ph0, ph1, ph2, ph3, vh[2], vh[3]);
                mma16816(oacc[2 * p + 1], ph0, ph1, ph2, ph3, vo[2], vo[3]);
                mma16816(oacc[2 * p + 1], pl0, pl1, pl2, pl3, vh[2], vh[3]);
            }
        }

        if (c + 1 < nchunk) {   // prefetch next K/V chunk
            __syncthreads();    // all warps done with current K/V smem
            size_t nb = (size_t)(b * 4 + c + 1) * TILE_U32;
            cpa_tile<256>(smb + 8 * PT_U32, g_kh + nb, tid);
            cpa_tile<256>(smb + 12 * PT_U32, g_kl + nb, tid);
            CP_COMMIT();
            cpa_tile<256>(smb + 16 * PT_U32, g_vvh + nb, tid);
            cpa_tile<256>(smb + 20 * PT_U32, g_vvl + nb, tid);
            CP_COMMIT();
        }
    }

    // ---- row sums + epilogue with analytic mask fold ----
    ps0 += __shfl_xor_sync(0xffffffffu, ps0, 1);
    ps0 += __shfl_xor_sync(0xffffffffu, ps0, 2);
    ps1 += __shfl_xor_sync(0xffffffffu, ps1, 1);
    ps1 += __shfl_xor_sync(0xffffffffu, ps1, 2);
    float wm = __expf(MASKF);
    float nm = (float)(N_ - 1 - vl) * wm;
    float rt0 = 1.f / (ps0 + nm);
    float rt1 = 1.f / (ps1 + nm);
    const float* vs = g_vsuf + b * 128;
    size_t rg = (size_t)b * N_ + qt * 128 + r0 + g;
#pragma unroll
    for (int nt = 0; nt < 16; nt++) {
        int col = 8 * nt + 2 * t;
        float v0 = __ldg(vs + col), v1 = __ldg(vs + col + 1);
        float2 o0 = make_float2((oacc[nt][0] + wm * v0) * rt0,
                                (oacc[nt][1] + wm * v1) * rt0);
        float2 o1 = make_float2((oacc[nt][2] + wm * v0) * rt1,
                                (oacc[nt][3] + wm * v1) * rt1);
        *(float2*)(out + rg * 128 + col) = o0;
        *(float2*)(out + (rg + 8) * 128 + col) = o1;
    }
}

// ---- launch ----
extern "C" void kernel_launch(void* const* d_in, const int* in_sizes, int n_in,
                              void* d_out, int out_size) {
    const float* x  = (const float*)d_in[0];
    const float* Wq = (const float*)d_in[1];
    const float* bq = (const float*)d_in[2];
    const float* Wk = (const float*)d_in[3];
    const float* bk = (const float*)d_in[4];
    const float* Wv = (const float*)d_in[5];
    const float* bv = (const float*)d_in[6];
    const void*  vl = d_in[7];

    cudaFuncSetAttribute(qkv_kernel, cudaFuncAttributeMaxDynamicSharedMemorySize, QKV_SMEM);
    cudaFuncSetAttribute(attn_kernel, cudaFuncAttributeMaxDynamicSharedMemorySize, ATTN_SMEM);

    decode_vl_kernel<<<1, 128>>>(vl);
    prep_all_kernel<<<B_ * 4 + 3, 256>>>(x, Wq, Wk, Wv);
    vsuf_gemv_kernel<<<B_, 256>>>(Wv, bv);
    qkv_kernel<<<dim3(B_ * 4, 3), 512, QKV_SMEM>>>(bq, bk, bv);
    attn_kernel<<<dim3(4, B_), 256, ATTN_SMEM>>>((float*)d_out);
}

// round 17
// speedup vs baseline: 3.0453x; 1.0158x over previous
#include <cuda_runtime.h>
#include <cuda_bf16.h>
#include <cstdint>

#define B_ 128
#define N_ 512
#define MASKF (-1e-6f)

#define TILE_U32 8192        // 128x128 bf16 tile = 128 rows x 64 u32 (unpadded)
#define PROW 68              // padded SMEM row stride (u32) = 272B
#define PT_U32 (128 * PROW)  // padded tile u32 count

// ---- global scratch (static: allocation-free) ----
__device__ __align__(16) uint32_t g_xh[(size_t)B_ * 4 * TILE_U32];
__device__ __align__(16) uint32_t g_xl[(size_t)B_ * 4 * TILE_U32];
__device__ __align__(16) uint32_t g_qh[(size_t)B_ * 4 * TILE_U32];
__device__ __align__(16) uint32_t g_ql[(size_t)B_ * 4 * TILE_U32];
__device__ __align__(16) uint32_t g_kh[(size_t)B_ * 4 * TILE_U32];
__device__ __align__(16) uint32_t g_kl[(size_t)B_ * 4 * TILE_U32];
__device__ __align__(16) uint32_t g_vvh[(size_t)B_ * 4 * TILE_U32];  // V K-major
__device__ __align__(16) uint32_t g_vvl[(size_t)B_ * 4 * TILE_U32];
__device__ __align__(16) uint32_t g_wth[3 * TILE_U32];  // W^T hi (q,k,v)
__device__ __align__(16) uint32_t g_wtl[3 * TILE_U32];
__device__ float g_xsum4[B_ * 4 * 128];  // per-tile masked-row column sums
__device__ float g_vsuf[B_ * 128];
__device__ int   g_vl[B_];

// ---- helpers ----
__device__ __forceinline__ uint32_t smem_u32(const void* p) {
    uint32_t a;
    asm("{ .reg .u64 t; cvta.to.shared.u64 t, %1; cvt.u32.u64 %0, t; }" : "=r"(a) : "l"(p));
    return a;
}
// fast two-term bf16 split of a float pair: h = [bf(f1)|bf(f0)], l = residuals
__device__ __forceinline__ void split_pack(float f0, float f1,
                                           uint32_t& h, uint32_t& l) {
    asm("cvt.rn.bf16x2.f32 %0, %1, %2;" : "=r"(h) : "f"(f1), "f"(f0));
    float hf0 = __uint_as_float(h << 16);
    float hf1 = __uint_as_float(h & 0xffff0000u);
    float l0 = f0 - hf0, l1 = f1 - hf1;
    asm("cvt.rn.bf16x2.f32 %0, %1, %2;" : "=r"(l) : "f"(l1), "f"(l0));
}
__device__ __forceinline__ void mma16816(float c[4], uint32_t a0, uint32_t a1,
                                         uint32_t a2, uint32_t a3,
                                         uint32_t b0, uint32_t b1) {
    asm volatile(
        "mma.sync.aligned.m16n8k16.row.col.f32.bf16.bf16.f32 "
        "{%0,%1,%2,%3}, {%4,%5,%6,%7}, {%8,%9}, {%0,%1,%2,%3};"
        : "+f"(c[0]), "+f"(c[1]), "+f"(c[2]), "+f"(c[3])
        : "r"(a0), "r"(a1), "r"(a2), "r"(a3), "r"(b0), "r"(b1));
}
__device__ __forceinline__ void mma3x(float c[4], const uint32_t ah[4],
                                      const uint32_t al[4],
                                      uint32_t bh0, uint32_t bh1,
                                      uint32_t bl0, uint32_t bl1) {
    mma16816(c, ah[0], ah[1], ah[2], ah[3], bh0, bh1);
    mma16816(c, ah[0], ah[1], ah[2], ah[3], bl0, bl1);
    mma16816(c, al[0], al[1], al[2], al[3], bh0, bh1);
}
#define LDSM4(R, a)                                                            \
    asm volatile("ldmatrix.sync.aligned.m8n8.x4.shared.b16 {%0,%1,%2,%3}, [%4];" \
        : "=r"((R)[0]), "=r"((R)[1]), "=r"((R)[2]), "=r"((R)[3]) : "r"(a))
#define LDSM4T(R, a)                                                           \
    asm volatile("ldmatrix.sync.aligned.m8n8.x4.trans.shared.b16 {%0,%1,%2,%3}, [%4];" \
        : "=r"((R)[0]), "=r"((R)[1]), "=r"((R)[2]), "=r"((R)[3]) : "r"(a))
#define CP16(saddr, gptr)                                                      \
    asm volatile("cp.async.cg.shared.global [%0], [%1], 16;" :: "r"(saddr), "l"(gptr))
#define CP_COMMIT() asm volatile("cp.async.commit_group;" ::: "memory")
#define CP_WAIT(n)  asm volatile("cp.async.wait_group %0;" :: "n"(n) : "memory")

// cp.async one unpadded 32KB tile -> padded smem (stride 17 float4/row-of-16)
template <int NT>
__device__ __forceinline__ void cpa_tile(uint32_t dst_byte, const uint32_t* src, int tid) {
    const float4* s4 = (const float4*)src;
#pragma unroll
    for (int i = tid; i < 2048; i += NT)
        CP16(dst_byte + ((i >> 4) * 17 + (i & 15)) * 16, s4 + i);
}
// degree-6 exp2 polynomial exp (FFMA pipe); valid for |x| <~ 80
__device__ __forceinline__ float exp_poly(float x) {
    float y = x * 1.4426950408889634f;
    int ni = __float2int_rn(y);
    float f = y - __int2float_rn(ni);
    float p = 1.54035e-4f;
    p = fmaf(p, f, 1.33336e-3f);
    p = fmaf(p, f, 9.61813e-3f);
    p = fmaf(p, f, 5.55041e-2f);
    p = fmaf(p, f, 2.402265e-1f);
    p = fmaf(p, f, 6.931472e-1f);
    p = fmaf(p, f, 1.0f);
    return __int_as_float(__float_as_int(p) + (ni << 23));
}

// ---- decode valid_len (runtime int64-vs-int32 detect) ----
__global__ __launch_bounds__(128)
void decode_vl_kernel(const void* __restrict__ raw) {
    __shared__ int bad;
    int t = threadIdx.x;
    if (t == 0) bad = 0;
    __syncthreads();
    if (t < 64) {
        long long v = ((const long long*)raw)[t];
        if (v < 0 || v >= N_) atomicOr(&bad, 1);
    }
    __syncthreads();
    if (t < B_) g_vl[t] = bad ? ((const int*)raw)[t] : (int)((const long long*)raw)[t];
}

// ---- merged prep: blocks 0-2 W^T tiles; blocks 3.. x-split + fused xsum ----
__global__ __launch_bounds__(256)
void prep_all_kernel(const float* __restrict__ x, const float* __restrict__ Wq,
                     const float* __restrict__ Wk, const float* __restrict__ Wv) {
    __shared__ float sxs[128];
    int blk = blockIdx.x, tid = threadIdx.x;
    if (blk < 3) {
        const float* W = (blk == 0) ? Wq : (blk == 1) ? Wk : Wv;
        int w = tid & 127;
        int c0 = (tid >> 7) * 64;  // two half-ranges of c per w
        size_t base = (size_t)blk * TILE_U32;
        for (int c = c0; c < c0 + 64; c += 2) {
            uint32_t h, l;
            split_pack(W[c * 128 + w], W[(c + 1) * 128 + w], h, l);
            g_wth[base + w * 64 + (c >> 1)] = h;
            g_wtl[base + w * 64 + (c >> 1)] = l;
        }
    } else {
        int xb = blk - 3;
        int b = xb >> 2, tile = xb & 3;
        int vl = g_vl[b];
        int lo = vl + 1 - tile * 128;       // first masked local row
        if (lo < 0) lo = 0;
        bool anymask = (lo < 128);
        if (tid < 128) sxs[tid] = 0.f;
        __syncthreads();
        const float4* xg = (const float4*)(x + (size_t)xb * 128 * 128);
        uint2* dh = (uint2*)(g_xh + (size_t)xb * TILE_U32);
        uint2* dl = (uint2*)(g_xl + (size_t)xb * TILE_U32);
#pragma unroll
        for (int i = tid; i < 4096; i += 256) {
            float4 v = xg[i];
            uint32_t h0, l0, h1, l1;
            split_pack(v.x, v.y, h0, l0);
            split_pack(v.z, v.w, h1, l1);
            dh[i] = make_uint2(h0, h1);
            dl[i] = make_uint2(l0, l1);
            if (anymask && (i >> 5) >= lo) {   // masked row: fold into column sums
                int c4 = (i & 31) << 2;
                atomicAdd(&sxs[c4], v.x);
                atomicAdd(&sxs[c4 + 1], v.y);
                atomicAdd(&sxs[c4 + 2], v.z);
                atomicAdd(&sxs[c4 + 3], v.w);
            }
        }
        __syncthreads();
        if (tid < 128) g_xsum4[xb * 128 + tid] = sxs[tid];
    }
}

// ---- vsuf[b][w] = (sum of 4 tile slots)@Wv + cnt*bv; 2-way c-split ----
__global__ __launch_bounds__(256)
void vsuf_gemv_kernel(const float* __restrict__ Wv, const float* __restrict__ bv) {
    __shared__ float xs[128];
    __shared__ float pacc[2][128];
    int b = blockIdx.x, tid = threadIdx.x;
    int vl = g_vl[b];
    if (tid < 128) {
        int base = b * 4 * 128 + tid;
        xs[tid] = g_xsum4[base] + g_xsum4[base + 128] +
                  g_xsum4[base + 256] + g_xsum4[base + 384];
    }
    __syncthreads();
    int w = tid & 127, half = tid >> 7;
    float acc = 0.f;
    int c0 = half * 64;
#pragma unroll 16
    for (int c = c0; c < c0 + 64; c++)
        acc = fmaf(xs[c], __ldg(Wv + c * 128 + w), acc);
    pacc[half][w] = acc;
    __syncthreads();
    if (tid < 128)
        g_vsuf[b * 128 + tid] = pacc[0][tid] + pacc[1][tid] +
                                (float)(N_ - 1 - vl) * __ldg(bv + tid);
}

// ===========================================================================
// QKV: grid (512, 3), 512 threads (16 warps). Warp tile 32x32 (wr rows, wc
// cols). Manual double-buffered fragment pipeline: stage s+1 LDSMs issue
// before stage s MMAs. 3-term bf16 GEMM. Fully-masked K/V tiles skipped.
// ===========================================================================
#define QKV_SMEM (16 * PT_U32)
#define QKV_LOAD(buf, s) do {                                                  \
    LDSM4(AH[buf][0], a_base + 32 * (s));                                      \
    LDSM4(AH[buf][1], a_base + 4352 + 32 * (s));                               \
    LDSM4(AL[buf][0], a_base + 4 * PT_U32 + 32 * (s));                         \
    LDSM4(AL[buf][1], a_base + 4 * PT_U32 + 4352 + 32 * (s));                  \
    LDSM4(BH[buf][0], b_base + 32 * (s));                                      \
    LDSM4(BH[buf][1], b_base + 4352 + 32 * (s));                               \
    LDSM4(BL[buf][0], b_base + 4 * PT_U32 + 32 * (s));                         \
    LDSM4(BL[buf][1], b_base + 4 * PT_U32 + 4352 + 32 * (s));                  \
} while (0)

__global__ __launch_bounds__(512)
void qkv_kernel(const float* __restrict__ bq, const float* __restrict__ bk,
                const float* __restrict__ bv) {
    extern __shared__ uint32_t smu[];
    int tid = threadIdx.x, warp = tid >> 5, lane = tid & 31;
    int g = lane >> 2, t = lane & 3;
    int wr = warp & 3, wc = warp >> 2;          // 4x4 warp grid, 32x32 tiles
    int blk = blockIdx.x, mat = blockIdx.y;
    int b = blk >> 2, tile = blk & 3, vl = g_vl[b];
    if (mat && tile * 128 > vl) return;

    uint32_t smb = smem_u32(smu);
    cpa_tile<512>(smb, g_xh + (size_t)blk * TILE_U32, tid);
    cpa_tile<512>(smb + 4 * PT_U32, g_xl + (size_t)blk * TILE_U32, tid);
    cpa_tile<512>(smb + 8 * PT_U32, g_wth + (size_t)mat * TILE_U32, tid);
    cpa_tile<512>(smb + 12 * PT_U32, g_wtl + (size_t)mat * TILE_U32, tid);
    CP_COMMIT();
    CP_WAIT(0);
    __syncthreads();

    float acc[8][4];
#pragma unroll
    for (int nt = 0; nt < 8; nt++)
#pragma unroll
        for (int i = 0; i < 4; i++) acc[nt][i] = 0.f;

    uint32_t a_base = smb + 4 * ((wr * 32 + (lane & 15)) * PROW + ((lane & 16) >> 2));
    uint32_t b_base = smb + 8 * PT_U32 + wc * 8704 +
                      4 * (((lane & 7) + ((lane & 16) >> 1)) * PROW + ((lane & 8) >> 1));

    uint32_t AH[2][2][4], AL[2][2][4], BH[2][2][4], BL[2][2][4];
    QKV_LOAD(0, 0);
#pragma unroll
    for (int s = 0; s < 8; s++) {
        int cur = s & 1, nxt = cur ^ 1;
        if (s < 7) QKV_LOAD(nxt, s + 1);
#pragma unroll
        for (int rt = 0; rt < 2; rt++)
#pragma unroll
            for (int j = 0; j < 2; j++) {
                mma3x(acc[rt * 4 + j * 2], AH[cur][rt], AL[cur][rt],
                      BH[cur][j][0], BH[cur][j][1], BL[cur][j][0], BL[cur][j][1]);
                mma3x(acc[rt * 4 + j * 2 + 1], AH[cur][rt], AL[cur][rt],
                      BH[cur][j][2], BH[cur][j][3], BL[cur][j][2], BL[cur][j][3]);
            }
    }

    const float* bias = (mat == 0) ? bq : (mat == 1) ? bk : bv;
    uint32_t* dh = (mat == 0) ? g_qh : (mat == 1) ? g_kh : g_vvh;
    uint32_t* dl = (mat == 0) ? g_ql : (mat == 1) ? g_kl : g_vvl;
#pragma unroll
    for (int rt = 0; rt < 2; rt++) {
        size_t rg = (size_t)blk * 128 + wr * 32 + rt * 16 + g;
#pragma unroll
        for (int nc = 0; nc < 4; nc++) {
            int col = wc * 32 + 8 * nc + 2 * t;
            float b0 = __ldg(bias + col), b1 = __ldg(bias + col + 1);
            uint32_t h, l;
            split_pack(acc[rt * 4 + nc][0] + b0, acc[rt * 4 + nc][1] + b1, h, l);
            dh[rg * 64 + (col >> 1)] = h;
            dl[rg * 64 + (col >> 1)] = l;
            split_pack(acc[rt * 4 + nc][2] + b0, acc[rt * 4 + nc][3] + b1, h, l);
            dh[(rg + 8) * 64 + (col >> 1)] = h;
            dl[(rg + 8) * 64 + (col >> 1)] = l;
        }
    }
}

// ===========================================================================
// Attention: grid (4, 128) — qt fastest so same-batch blocks share K/V in L2.
// ldmatrix fragments, hybrid exp, cp.async prefetch, unroll-2 S k-loop.
// ===========================================================================
#define ATTN_SMEM (24 * PT_U32)
__global__ __launch_bounds__(256)
void attn_kernel(float* __restrict__ out) {
    extern __shared__ uint32_t smu[];
    int tid = threadIdx.x, warp = tid >> 5, lane = tid & 31;
    int g = lane >> 2, t = lane & 3, r0 = warp * 16;
    int qt = blockIdx.x, b = blockIdx.y;
    int vl = g_vl[b], nchunk = (vl >> 7) + 1;
    uint32_t smb = smem_u32(smu);

    size_t qb = (size_t)(b * 4 + qt) * TILE_U32;
    cpa_tile<256>(smb, g_qh + qb, tid);
    cpa_tile<256>(smb + 4 * PT_U32, g_ql + qb, tid);
    CP_COMMIT();
    size_t kb0 = (size_t)(b * 4) * TILE_U32;
    cpa_tile<256>(smb + 8 * PT_U32, g_kh + kb0, tid);
    cpa_tile<256>(smb + 12 * PT_U32, g_kl + kb0, tid);
    CP_COMMIT();
    cpa_tile<256>(smb + 16 * PT_U32, g_vvh + kb0, tid);
    cpa_tile<256>(smb + 20 * PT_U32, g_vvl + kb0, tid);
    CP_COMMIT();

    uint32_t qa = smb + 4 * ((r0 + (lane & 15)) * PROW + ((lane & 16) >> 2));
    uint32_t kbb = smb + 8 * PT_U32 +
                   4 * (((lane & 7) + ((lane & 16) >> 1)) * PROW + ((lane & 8) >> 1));
    uint32_t vbb = smb + 16 * PT_U32 +
                   4 * (((lane & 7) + (lane & 8)) * PROW + ((lane & 16) >> 2));

    float oacc[16][4];
#pragma unroll
    for (int nt = 0; nt < 16; nt++)
#pragma unroll
        for (int i = 0; i < 4; i++) oacc[nt][i] = 0.f;
    float ps0 = 0.f, ps1 = 0.f;

#pragma unroll 1
    for (int c = 0; c < nchunk; c++) {
        CP_WAIT(1);          // Q+K ready (V may still be in flight)
        __syncthreads();

        // ---- S = Q @ K^T ----
        float sacc[16][4];
#pragma unroll
        for (int nt = 0; nt < 16; nt++)
#pragma unroll
            for (int i = 0; i < 4; i++) sacc[nt][i] = 0.f;
#pragma unroll 2
        for (int s = 0; s < 8; s++) {
            uint32_t ah[4], al[4];
            LDSM4(ah, qa + 32 * s);
            LDSM4(al, qa + 4 * PT_U32 + 32 * s);
#pragma unroll
            for (int p = 0; p < 8; p++) {
                uint32_t bh[4], bl[4];
                LDSM4(bh, kbb + 4352 * p + 32 * s);
                LDSM4(bl, kbb + 4 * PT_U32 + 4352 * p + 32 * s);
                mma3x(sacc[2 * p], ah, al, bh[0], bh[1], bl[0], bl[1]);
                mma3x(sacc[2 * p + 1], ah, al, bh[2], bh[3], bl[2], bl[3]);
            }
        }

        // ---- masked exp (no max subtraction), hybrid MUFU/FFMA ----
        int cn = c * 128 + 2 * t;
#pragma unroll
        for (int nt = 0; nt < 16; nt++) {
            int n0 = cn + 8 * nt;
            float e0, e1, e2, e3;
            if (nt & 1) {
                e0 = exp_poly(sacc[nt][0]); e1 = exp_poly(sacc[nt][1]);
                e2 = exp_poly(sacc[nt][2]); e3 = exp_poly(sacc[nt][3]);
            } else {
                e0 = __expf(sacc[nt][0]); e1 = __expf(sacc[nt][1]);
                e2 = __expf(sacc[nt][2]); e3 = __expf(sacc[nt][3]);
            }
            e0 = (n0 <= vl) ? e0 : 0.f;
            e1 = (n0 + 1 <= vl) ? e1 : 0.f;
            e2 = (n0 <= vl) ? e2 : 0.f;
            e3 = (n0 + 1 <= vl) ? e3 : 0.f;
            ps0 += e0 + e1;
            ps1 += e2 + e3;
            sacc[nt][0] = e0; sacc[nt][1] = e1;
            sacc[nt][2] = e2; sacc[nt][3] = e3;
        }

        CP_WAIT(0);          // V ready
        __syncthreads();

        // ---- O += P @ V (P regs -> A-frags; V via ldmatrix.trans) ----
#pragma unroll
        for (int s = 0; s < 8; s++) {
            uint32_t ph0, pl0, ph1, pl1, ph2, pl2, ph3, pl3;
            split_pack(sacc[2 * s][0], sacc[2 * s][1], ph0, pl0);
            split_pack(sacc[2 * s][2], sacc[2 * s][3], ph1, pl1);
            split_pack(sacc[2 * s + 1][0], sacc[2 * s + 1][1], ph2, pl2);
            split_pack(sacc[2 * s + 1][2], sacc[2 * s + 1][3], ph3, pl3);
#pragma unroll
            for (int p = 0; p < 8; p++) {
                uint32_t vh[4], vo[4];
                LDSM4T(vh, vbb + 4352 * s + 32 * p);
                LDSM4T(vo, vbb + 4 * PT_U32 + 4352 * s + 32 * p);
                mma16816(oacc[2 * p], ph0, ph1, ph2, ph3, vh[0], vh[1]);
                mma16816(oacc[2 * p], ph0, ph1, ph2, ph3, vo[0], vo[1]);
                mma16816(oacc[2 * p], pl0, pl1, pl2, pl3, vh[0], vh[1]);
                mma16816(oacc[2 * p + 1], ph0, ph1, ph2, ph3, vh[2], vh[3]);
                mma16816(oacc[2 * p + 1], ph0, ph1, ph2, ph3, vo[2], vo[3]);
                mma16816(oacc[2 * p + 1], pl0, pl1, pl2, pl3, vh[2], vh[3]);
            }
        }

        if (c + 1 < nchunk) {   // prefetch next K/V chunk
            __syncthreads();    // all warps done with current K/V smem
            size_t nb = (size_t)(b * 4 + c + 1) * TILE_U32;
            cpa_tile<256>(smb + 8 * PT_U32, g_kh + nb, tid);
            cpa_tile<256>(smb + 12 * PT_U32, g_kl + nb, tid);
            CP_COMMIT();
            cpa_tile<256>(smb + 16 * PT_U32, g_vvh + nb, tid);
            cpa_tile<256>(smb + 20 * PT_U32, g_vvl + nb, tid);
            CP_COMMIT();
        }
    }

    // ---- row sums + epilogue with analytic mask fold ----
    ps0 += __shfl_xor_sync(0xffffffffu, ps0, 1);
    ps0 += __shfl_xor_sync(0xffffffffu, ps0, 2);
    ps1 += __shfl_xor_sync(0xffffffffu, ps1, 1);
    ps1 += __shfl_xor_sync(0xffffffffu, ps1, 2);
    float wm = __expf(MASKF);
    float nm = (float)(N_ - 1 - vl) * wm;
    float rt0 = 1.f / (ps0 + nm);
    float rt1 = 1.f / (ps1 + nm);
    const float* vs = g_vsuf + b * 128;
    size_t rg = (size_t)b * N_ + qt * 128 + r0 + g;
#pragma unroll
    for (int nt = 0; nt < 16; nt++) {
        int col = 8 * nt + 2 * t;
        float v0 = __ldg(vs + col), v1 = __ldg(vs + col + 1);
        float2 o0 = make_float2((oacc[nt][0] + wm * v0) * rt0,
                                (oacc[nt][1] + wm * v1) * rt0);
        float2 o1 = make_float2((oacc[nt][2] + wm * v0) * rt1,
                                (oacc[nt][3] + wm * v1) * rt1);
        *(float2*)(out + rg * 128 + col) = o0;
        *(float2*)(out + (rg + 8) * 128 + col) = o1;
    }
}

// ---- launch ----
extern "C" void kernel_launch(void* const* d_in, const int* in_sizes, int n_in,
                              void* d_out, int out_size) {
    const float* x  = (const float*)d_in[0];
    const float* Wq = (const float*)d_in[1];
    const float* bq = (const float*)d_in[2];
    const float* Wk = (const float*)d_in[3];
    const float* bk = (const float*)d_in[4];
    const float* Wv = (const float*)d_in[5];
    const float* bv = (const float*)d_in[6];
    const void*  vl = d_in[7];

    cudaFuncSetAttribute(qkv_kernel, cudaFuncAttributeMaxDynamicSharedMemorySize, QKV_SMEM);
    cudaFuncSetAttribute(attn_kernel, cudaFuncAttributeMaxDynamicSharedMemorySize, ATTN_SMEM);

    decode_vl_kernel<<<1, 128>>>(vl);
    prep_all_kernel<<<B_ * 4 + 3, 256>>>(x, Wq, Wk, Wv);
    vsuf_gemv_kernel<<<B_, 256>>>(Wv, bv);
    qkv_kernel<<<dim3(B_ * 4, 3), 512, QKV_SMEM>>>(bq, bk, bv);
    attn_kernel<<<dim3(4, B_), 256, ATTN_SMEM>>>((float*)d_out);
}